// round 12
// baseline (speedup 1.0000x reference)
#include <cuda_runtime.h>
#include <cuda_bf16.h>

#define BB 8
#define SS 16
#define TT 128
#define DD 64
#define NN 2048
#define P0  (0.00048828125f)   // 1/2048

typedef unsigned long long ull;
typedef unsigned int uint;

// bf16 split operands
__device__ __nv_bfloat16 g_qh[BB*NN*DD], g_ql[BB*NN*DD];
__device__ __nv_bfloat16 g_kh[BB*NN*DD], g_kl[BB*NN*DD];
__device__ __nv_bfloat16 g_vph[BB*NN*DD], g_vpl[BB*NN*DD]; // [b][m][d], m = t*16+s

__device__ __forceinline__ ull pk2(float x, float y){
    ull r; asm("mov.b64 %0, {%1, %2};" : "=l"(r) : "f"(x), "f"(y)); return r;
}
__device__ __forceinline__ void fma2(ull &d, ull a, ull b){
    asm("fma.rn.f32x2 %0, %1, %2, %0;" : "+l"(d) : "l"(a), "l"(b));
}
__device__ __forceinline__ float2 upk2(ull v){
    float2 r; asm("mov.b64 {%0, %1}, %2;" : "=f"(r.x), "=f"(r.y) : "l"(v)); return r;
}

// ---------------- kernel 1: QKV projection -> bf16 splits (1 wave) ----------------
__global__ void __launch_bounds__(512)
qkv_kernel(const float* __restrict__ x,
           const float* __restrict__ Wq_w, const float* __restrict__ Wq_b,
           const float* __restrict__ Wk_w, const float* __restrict__ Wk_b,
           const float* __restrict__ Wv_w, const float* __restrict__ Wv_b)
{
    extern __shared__ float sm1[];
    float* xs = sm1;               // [128][68]
    float* wt = xs + 128*68;       // [3][64][68]
    float* bs = wt + 3*64*68;      // [3][64]

    int tid = threadIdx.x;
    int r0  = blockIdx.x * 128;

    for (int idx = tid; idx < 64*64; idx += 512) {
        int c = idx >> 6, kk = idx & 63;
        wt[(0*64 + kk)*68 + c] = Wq_w[idx];
        wt[(1*64 + kk)*68 + c] = Wk_w[idx];
        wt[(2*64 + kk)*68 + c] = Wv_w[idx];
    }
    if (tid < 64) {
        bs[tid]       = Wq_b[tid];
        bs[64 + tid]  = Wk_b[tid];
        bs[128 + tid] = Wv_b[tid];
    }
    #pragma unroll
    for (int it = 0; it < 4; it++) {
        int idx = tid + (it << 9);
        int r = idx >> 4, f = idx & 15;
        float4 v = *(const float4*)(x + (size_t)(r0 + r)*64 + (f << 2));
        *(float4*)&xs[r*68 + (f << 2)] = v;
    }
    __syncthreads();

    int cg   = tid & 7;
    int rg   = tid >> 3;
    int row0 = rg << 1;
    const float* x0p = &xs[row0 * 68];
    const float* x1p = x0p + 68;
    int gr0 = r0 + row0;
    int b_  = gr0 >> 11;

    for (int mat = 0; mat < 3; mat++) {
        ull a0[4], a1[4];
        {
            const ulonglong2* bp = (const ulonglong2*)(bs + mat*64 + 8*cg);
            ulonglong2 b01 = bp[0], b23 = bp[1];
            a0[0]=b01.x; a0[1]=b01.y; a0[2]=b23.x; a0[3]=b23.y;
            a1[0]=b01.x; a1[1]=b01.y; a1[2]=b23.x; a1[3]=b23.y;
        }
        const float* wp = &wt[mat*64*68 + 8*cg];
        #pragma unroll 4
        for (int kk = 0; kk < 64; kk++) {
            float q0 = x0p[kk], q1 = x1p[kk];
            ull q0p = pk2(q0, q0), q1p = pk2(q1, q1);
            ulonglong2 w01 = *(const ulonglong2*)(wp + kk*68);
            ulonglong2 w23 = *(const ulonglong2*)(wp + kk*68 + 4);
            fma2(a0[0], q0p, w01.x); fma2(a0[1], q0p, w01.y);
            fma2(a0[2], q0p, w23.x); fma2(a0[3], q0p, w23.y);
            fma2(a1[0], q1p, w01.x); fma2(a1[1], q1p, w01.y);
            fma2(a1[2], q1p, w23.x); fma2(a1[3], q1p, w23.y);
        }
        #pragma unroll
        for (int rr = 0; rr < 2; rr++) {
            int gr = gr0 + rr;
            ull* ap = rr ? a1 : a0;
            float f[8];
            { float2 u0=upk2(ap[0]),u1=upk2(ap[1]),u2=upk2(ap[2]),u3=upk2(ap[3]);
              f[0]=u0.x; f[1]=u0.y; f[2]=u1.x; f[3]=u1.y;
              f[4]=u2.x; f[5]=u2.y; f[6]=u3.x; f[7]=u3.y; }
            __nv_bfloat16 h[8]; __nv_bfloat16 lo[8];
            #pragma unroll
            for (int i = 0; i < 8; i++) {
                h[i]  = __float2bfloat16(f[i]);
                lo[i] = __float2bfloat16(f[i] - __bfloat162float(h[i]));
            }
            if (mat < 2) {
                __nv_bfloat16* dh = (mat == 0) ? g_qh : g_kh;
                __nv_bfloat16* dl = (mat == 0) ? g_ql : g_kl;
                *(uint4*)(dh + (size_t)gr*64 + 8*cg) = *(uint4*)h;
                *(uint4*)(dl + (size_t)gr*64 + 8*cg) = *(uint4*)lo;
            } else {
                int n = gr & 2047;
                int s_ = n >> 7, t_ = n & 127;
                int m  = t_*16 + s_;
                *(uint4*)(g_vph + ((size_t)(b_ << 11) + m)*64 + 8*cg) = *(uint4*)h;
                *(uint4*)(g_vpl + ((size_t)(b_ << 11) + m)*64 + 8*cg) = *(uint4*)lo;
            }
        }
    }
}

// ---------------- attention (1024 threads) ----------------
#define OFF_QH 0
#define OFF_QL 16384
#define OFF_K0 32768
#define OFF_K0L 49152
#define OFF_K1 65536
#define OFF_K1L 81920
#define OFF_VH 98304
#define OFF_VL 114688
#define OFF_PH 131072
#define OFF_PL 163840
#define OFF_MSB  196608
#define OFF_STLP 198656    // 128*4 floats
#define OFF_UF   200704
#define OFF_FLAG 201216
#define OFF_TAGS 201220
#define SMEM_AT  201472

#define QOFF(r,c) ((uint)((r)*128 + (((c) ^ ((r)&7)) << 4)))
#define VOFF(r,c) ((uint)((r)*256 + (((c) ^ ((r)&7)) << 4)))

__device__ __forceinline__ uint smem_u32(const void* p){
    uint a; asm("{ .reg .u64 t; cvta.to.shared.u64 t, %1; cvt.u32.u64 %0, t; }" : "=r"(a) : "l"(p));
    return a;
}
__device__ __forceinline__ void cpa16(uint dst, const void* src){
    asm volatile("cp.async.cg.shared.global [%0], [%1], 16;"
        :: "r"(dst), "l"(__cvta_generic_to_global(src)) : "memory");
}
#define CPA_COMMIT() asm volatile("cp.async.commit_group;" ::: "memory")
#define CPA_WAIT0()  asm volatile("cp.async.wait_group 0;" ::: "memory")
#define CPA_WAIT1()  asm volatile("cp.async.wait_group 1;" ::: "memory")

__device__ __forceinline__ uint4 ldsm4(uint addr){
    uint4 r;
    asm volatile("ldmatrix.sync.aligned.m8n8.x4.shared.b16 {%0,%1,%2,%3}, [%4];"
        : "=r"(r.x), "=r"(r.y), "=r"(r.z), "=r"(r.w) : "r"(addr));
    return r;
}
__device__ __forceinline__ uint4 ldsm4t(uint addr){
    uint4 r;
    asm volatile("ldmatrix.sync.aligned.m8n8.x4.trans.shared.b16 {%0,%1,%2,%3}, [%4];"
        : "=r"(r.x), "=r"(r.y), "=r"(r.z), "=r"(r.w) : "r"(addr));
    return r;
}
__device__ __forceinline__ void mma16816(float* d, uint4 a, uint b0, uint b1){
    asm volatile("mma.sync.aligned.m16n8k16.row.col.f32.bf16.bf16.f32 "
        "{%0,%1,%2,%3}, {%4,%5,%6,%7}, {%8,%9}, {%0,%1,%2,%3};"
        : "+f"(d[0]), "+f"(d[1]), "+f"(d[2]), "+f"(d[3])
        : "r"(a.x), "r"(a.y), "r"(a.z), "r"(a.w), "r"(b0), "r"(b1));
}

__global__ void __launch_bounds__(1024, 1)
attn_kernel(const int* __restrict__ tags, const float* __restrict__ mask,
            float* __restrict__ ctx, float* __restrict__ p)
{
    extern __shared__ char smem[];
    uint sb = smem_u32(smem);
    int tid  = threadIdx.x;
    int wid  = tid >> 5, lane = tid & 31;
    int wr   = wid >> 2;                 // row group 0..7
    int wq   = wid & 3;                  // col quarter 0..3
    int m0   = wr << 4;
    int nb   = wq << 5;                  // QK col base (32 cols)
    int db   = wq << 4;                  // AV d base (16 cols)
    int s    = blockIdx.x;
    int b    = blockIdx.y;
    int lq   = lane & 3;
    int lr   = lane >> 2;
    int rA   = m0 + lr, rB = rA + 8;

    int*   tgs  = (int*)(smem + OFF_TAGS);
    uint*  msb  = (uint*)(smem + OFF_MSB);
    float* stlp = (float*)(smem + OFF_STLP);
    int*   ufr  = (int*)(smem + OFF_UF);
    int*   flg  = (int*)(smem + OFF_FLAG);

    if (tid < 16) tgs[tid] = tags[b*16 + tid];
    if (tid == 0) flg[0] = 0;
    if (tid < 512) {
        int tt = tid >> 2, w = tid & 3;
        uint bits = 0;
        #pragma unroll 8
        for (int j = 0; j < 32; j++)
            bits |= (mask[(size_t)tt*128 + w*32 + j] != 0.f ? 1u : 0u) << j;
        msb[tid] = bits;
    }
    // stage Q (cp.async), 1024 (r,c) pairs
    {
        int r = tid >> 3, c = tid & 7;
        size_t se = ((size_t)((b << 11) + (s << 7) + r))*64 + c*8;
        cpa16(sb + OFF_QH + QOFF(r, c), g_qh + se);
        cpa16(sb + OFF_QL + QOFF(r, c), g_ql + se);
    }
    CPA_COMMIT();
    __syncthreads();

    int mytag = tgs[s];
    uint vmask = 0;
    #pragma unroll
    for (int s2 = 0; s2 < 16; s2++) if (tgs[s2] == mytag) vmask |= 1u << s2;
    int vlist[16], nv = 0;
    #pragma unroll
    for (int s2 = 0; s2 < 16; s2++) if ((vmask >> s2) & 1) vlist[nv++] = s2;

    uint mbA = 0, mbB = 0;
    #pragma unroll
    for (int f = 0; f < 4; f++)
        #pragma unroll
        for (int u = 0; u < 2; u++) {
            int cw = nb + 8*f + 2*lq + u;
            mbA |= ((msb[rA*4 + (cw >> 5)] >> (cw & 31)) & 1u) << (f*2 + u);
            mbB |= ((msb[rB*4 + (cw >> 5)] >> (cw & 31)) & 1u) << (f*2 + u);
        }

    int aRow = m0 + (lane & 7) + ((lane >> 3) & 1)*8;
    int aChS = (lane >> 4);
    int bRowOff = (lane & 7) + ((lane >= 16) ? 8 : 0);
    int bChS = ((lane >> 3) & 1);
    int vRowOff = (lane & 7) + (((lane >> 3) & 1) << 3);
    int vChS = (lane >> 4);

    const __nv_bfloat16* gb_kh = g_kh + ((size_t)b << 17);
    const __nv_bfloat16* gb_kl = g_kl + ((size_t)b << 17);
    const __nv_bfloat16* gb_vh = g_vph + ((size_t)b << 17);
    const __nv_bfloat16* gb_vl = g_vpl + ((size_t)b << 17);

    // ================ pass 1: l = sum exp(s), (qh+ql)*kh ================
    float lsA = 0.f, lsB = 0.f;
    {
        {
            int r = tid >> 3, c = tid & 7;
            cpa16(sb + OFF_K0 + QOFF(r, c), gb_kh + ((size_t)((vlist[0] << 7) + r))*64 + c*8);
        }
        CPA_COMMIT();
        for (int vi = 0; vi < nv; vi++) {
            CPA_WAIT0();
            __syncthreads();
            if (vi + 1 < nv) {
                uint dsto = ((vi + 1) & 1) ? OFF_K1 : OFF_K0;
                int r = tid >> 3, c = tid & 7;
                cpa16(sb + dsto + QOFF(r, c), gb_kh + ((size_t)((vlist[vi+1] << 7) + r))*64 + c*8);
                CPA_COMMIT();
            }
            uint kb = sb + ((vi & 1) ? OFF_K1 : OFF_K0);
            float acc[4][4];
            #pragma unroll
            for (int f = 0; f < 4; f++) { acc[f][0]=0; acc[f][1]=0; acc[f][2]=0; acc[f][3]=0; }
            #pragma unroll
            for (int ks = 0; ks < 4; ks++) {
                uint4 Ah = ldsm4(sb + OFF_QH + QOFF(aRow, 2*ks + aChS));
                uint4 Al = ldsm4(sb + OFF_QL + QOFF(aRow, 2*ks + aChS));
                #pragma unroll
                for (int fp = 0; fp < 2; fp++) {
                    int n = nb + 16*fp;
                    uint4 Bv = ldsm4(kb + QOFF(n + bRowOff, 2*ks + bChS));
                    mma16816(acc[2*fp],     Ah, Bv.x, Bv.y);
                    mma16816(acc[2*fp + 1], Ah, Bv.z, Bv.w);
                    mma16816(acc[2*fp],     Al, Bv.x, Bv.y);
                    mma16816(acc[2*fp + 1], Al, Bv.z, Bv.w);
                }
            }
            #pragma unroll
            for (int f = 0; f < 4; f++) {
                lsA += (((mbA >> (2*f)) & 1)   ? __expf(acc[f][0]*0.125f) : 0.f)
                     + (((mbA >> (2*f+1)) & 1) ? __expf(acc[f][1]*0.125f) : 0.f);
                lsB += (((mbB >> (2*f)) & 1)   ? __expf(acc[f][2]*0.125f) : 0.f)
                     + (((mbB >> (2*f+1)) & 1) ? __expf(acc[f][3]*0.125f) : 0.f);
            }
        }
    }
    lsA += __shfl_xor_sync(0xffffffffu, lsA, 1);
    lsA += __shfl_xor_sync(0xffffffffu, lsA, 2);
    lsB += __shfl_xor_sync(0xffffffffu, lsB, 1);
    lsB += __shfl_xor_sync(0xffffffffu, lsB, 2);
    __syncthreads();
    if (lq == 0) { stlp[rA*4 + wq] = lsA; stlp[rB*4 + wq] = lsB; }
    __syncthreads();
    float lA = stlp[rA*4] + stlp[rA*4+1] + stlp[rA*4+2] + stlp[rA*4+3];
    float lB = stlp[rB*4] + stlp[rB*4+1] + stlp[rB*4+2] + stlp[rB*4+3];
    int ufA = (lA == 0.f), ufB = (lB == 0.f);
    float invlA = ufA ? 0.f : 1.f/lA;
    float invlB = ufB ? 0.f : 1.f/lB;
    if (lq == 0 && wq == 0) { ufr[rA] = ufA; ufr[rB] = ufB; if (ufA | ufB) flg[0] = 1; }
    __syncthreads();
    int anyU = flg[0];

    // ================ pass 2: p + AV ================
    int nproc = anyU ? 16 : nv;
    float accAV[2][4];
    accAV[0][0]=0; accAV[0][1]=0; accAV[0][2]=0; accAV[0][3]=0;
    accAV[1][0]=0; accAV[1][1]=0; accAV[1][2]=0; accAV[1][3]=0;
    float* pbase = p + ((size_t)(b*2048 + s*128))*2048;

    {
        int blk0 = anyU ? 0 : vlist[0];
        int r = tid >> 3, c = tid & 7;
        size_t se = ((size_t)((blk0 << 7) + r))*64 + c*8;
        cpa16(sb + OFF_K0  + QOFF(r, c), gb_kh + se);
        cpa16(sb + OFF_K0L + QOFF(r, c), gb_kl + se);
        CPA_COMMIT();
    }

    for (int idx2 = 0; idx2 < nproc; idx2++) {
        int s2 = anyU ? idx2 : vlist[idx2];
        int bv = (vmask >> s2) & 1;
        CPA_WAIT0();
        __syncthreads();
        {
            int r = tid >> 3, c = tid & 7;
            size_t se = ((size_t)((s2 << 7) + r))*64 + c*8;
            cpa16(sb + OFF_VH + QOFF(r, c), gb_vh + se);
            cpa16(sb + OFF_VL + QOFF(r, c), gb_vl + se);
        }
        CPA_COMMIT();
        int havenext = (idx2 + 1 < nproc);
        if (havenext) {
            int s3 = anyU ? (idx2 + 1) : vlist[idx2 + 1];
            uint dh = ((idx2 + 1) & 1) ? OFF_K1 : OFF_K0;
            uint dl = ((idx2 + 1) & 1) ? OFF_K1L : OFF_K0L;
            int r = tid >> 3, c = tid & 7;
            size_t se = ((size_t)((s3 << 7) + r))*64 + c*8;
            cpa16(sb + dh + QOFF(r, c), gb_kh + se);
            cpa16(sb + dl + QOFF(r, c), gb_kl + se);
            CPA_COMMIT();
        }
        uint kbh = sb + ((idx2 & 1) ? OFF_K1 : OFF_K0);
        uint kbl = sb + ((idx2 & 1) ? OFF_K1L : OFF_K0L);
        if (bv) {
            float acc[4][4];
            #pragma unroll
            for (int f = 0; f < 4; f++) { acc[f][0]=0; acc[f][1]=0; acc[f][2]=0; acc[f][3]=0; }
            #pragma unroll
            for (int ks = 0; ks < 4; ks++) {
                uint4 Ah = ldsm4(sb + OFF_QH + QOFF(aRow, 2*ks + aChS));
                uint4 Al = ldsm4(sb + OFF_QL + QOFF(aRow, 2*ks + aChS));
                #pragma unroll
                for (int fp = 0; fp < 2; fp++) {
                    int n = nb + 16*fp;
                    uint4 Bh = ldsm4(kbh + QOFF(n + bRowOff, 2*ks + bChS));
                    mma16816(acc[2*fp],     Ah, Bh.x, Bh.y);
                    mma16816(acc[2*fp + 1], Ah, Bh.z, Bh.w);
                    mma16816(acc[2*fp],     Al, Bh.x, Bh.y);
                    mma16816(acc[2*fp + 1], Al, Bh.z, Bh.w);
                    uint4 Bl = ldsm4(kbl + QOFF(n + bRowOff, 2*ks + bChS));
                    mma16816(acc[2*fp],     Ah, Bl.x, Bl.y);
                    mma16816(acc[2*fp + 1], Ah, Bl.z, Bl.w);
                }
            }
            #pragma unroll
            for (int f = 0; f < 4; f++) {
                float e0 = ((mbA >> (2*f)) & 1)   ? __expf(acc[f][0]*0.125f) : 0.f;
                float e1 = ((mbA >> (2*f+1)) & 1) ? __expf(acc[f][1]*0.125f) : 0.f;
                float e2 = ((mbB >> (2*f)) & 1)   ? __expf(acc[f][2]*0.125f) : 0.f;
                float e3 = ((mbB >> (2*f+1)) & 1) ? __expf(acc[f][3]*0.125f) : 0.f;
                float p0 = ufA ? P0 : e0*invlA;
                float p1 = ufA ? P0 : e1*invlA;
                float p2 = ufB ? P0 : e2*invlB;
                float p3 = ufB ? P0 : e3*invlB;
                int cw = nb + 8*f + 2*lq;
                *(float2*)(pbase + (size_t)rA*2048 + s2*128 + cw) = make_float2(p0, p1);
                *(float2*)(pbase + (size_t)rB*2048 + s2*128 + cw) = make_float2(p2, p3);
                int ch = (wq << 2) + f;
                __nv_bfloat16 h0 = __float2bfloat16(p0), h1 = __float2bfloat16(p1);
                __nv_bfloat16 h2 = __float2bfloat16(p2), h3 = __float2bfloat16(p3);
                __nv_bfloat162 hA(h0, h1), hB(h2, h3);
                __nv_bfloat162 lA2(__float2bfloat16(p0 - __bfloat162float(h0)),
                                   __float2bfloat16(p1 - __bfloat162float(h1)));
                __nv_bfloat162 lB2(__float2bfloat16(p2 - __bfloat162float(h2)),
                                   __float2bfloat16(p3 - __bfloat162float(h3)));
                *(uint*)(smem + OFF_PH + VOFF(rA, ch) + 4*lq) = *(uint*)&hA;
                *(uint*)(smem + OFF_PL + VOFF(rA, ch) + 4*lq) = *(uint*)&lA2;
                *(uint*)(smem + OFF_PH + VOFF(rB, ch) + 4*lq) = *(uint*)&hB;
                *(uint*)(smem + OFF_PL + VOFF(rB, ch) + 4*lq) = *(uint*)&lB2;
            }
        } else {
            __nv_bfloat16 hp0 = __float2bfloat16(P0);
            __nv_bfloat162 hset(hp0, hp0);
            __nv_bfloat162 zset(__float2bfloat16(0.f), __float2bfloat16(0.f));
            for (int i = tid; i < 2048; i += 1024) {
                int r = i >> 4, c = i & 15;
                uint4 hv, zv;
                __nv_bfloat162 vv = ufr[r] ? hset : zset;
                hv.x = hv.y = hv.z = hv.w = *(uint*)&vv;
                zv.x = zv.y = zv.z = zv.w = *(uint*)&zset;
                *(uint4*)(smem + OFF_PH + VOFF(r, c)) = hv;
                *(uint4*)(smem + OFF_PL + VOFF(r, c)) = zv;
            }
            for (int i = tid; i < 4096; i += 1024) {
                int r = i >> 5, c4 = i & 31;
                float pv = ufr[r] ? P0 : 0.f;
                *(float4*)(pbase + (size_t)r*2048 + s2*128 + (c4 << 2)) =
                    make_float4(pv, pv, pv, pv);
            }
        }
        if (havenext) { CPA_WAIT1(); } else { CPA_WAIT0(); }
        __syncthreads();
        #pragma unroll
        for (int ks = 0; ks < 8; ks++) {
            uint4 Ah = ldsm4(sb + OFF_PH + VOFF(aRow, 2*ks + aChS));
            uint4 Al = ldsm4(sb + OFF_PL + VOFF(aRow, 2*ks + aChS));
            int cch = (db >> 3) + vChS;
            uint4 Bh = ldsm4t(sb + OFF_VH + QOFF(16*ks + vRowOff, cch));
            mma16816(accAV[0], Ah, Bh.x, Bh.y);
            mma16816(accAV[1], Ah, Bh.z, Bh.w);
            mma16816(accAV[0], Al, Bh.x, Bh.y);
            mma16816(accAV[1], Al, Bh.z, Bh.w);
            uint4 Bl = ldsm4t(sb + OFF_VL + QOFF(16*ks + vRowOff, cch));
            mma16816(accAV[0], Ah, Bl.x, Bl.y);
            mma16816(accAV[1], Ah, Bl.z, Bl.w);
        }
    }

    if (!anyU) {
        for (int s2 = 0; s2 < 16; s2++) {
            if ((vmask >> s2) & 1) continue;
            float4 z = make_float4(0.f, 0.f, 0.f, 0.f);
            for (int i = tid; i < 4096; i += 1024) {
                int r = i >> 5, c4 = i & 31;
                *(float4*)(pbase + (size_t)r*2048 + s2*128 + (c4 << 2)) = z;
            }
        }
    }

    {
        float* cb = ctx + ((size_t)(b*2048 + s*128))*64;
        #pragma unroll
        for (int f = 0; f < 2; f++) {
            int dc = db + 8*f + 2*lq;
            *(float2*)(cb + (size_t)rA*64 + dc) = make_float2(accAV[f][0], accAV[f][1]);
            *(float2*)(cb + (size_t)rB*64 + dc) = make_float2(accAV[f][2], accAV[f][3]);
        }
    }
}

#define SMEM1 ((128*68 + 3*64*68 + 3*64) * 4)

extern "C" void kernel_launch(void* const* d_in, const int* in_sizes, int n_in,
                              void* d_out, int out_size) {
    const float* x    = (const float*)d_in[0];
    const int*   tags = (const int*)  d_in[1];
    const float* mk   = (const float*)d_in[2];
    const float* Wk_w = (const float*)d_in[3];
    const float* Wk_b = (const float*)d_in[4];
    const float* Wq_w = (const float*)d_in[5];
    const float* Wq_b = (const float*)d_in[6];
    const float* Wv_w = (const float*)d_in[7];
    const float* Wv_b = (const float*)d_in[8];

    float* ctx = (float*)d_out;                        // [8,16,128,64]
    float* p   = ctx + (size_t)BB*SS*TT*DD;            // [8,2048,2048]

    cudaFuncSetAttribute(qkv_kernel,  cudaFuncAttributeMaxDynamicSharedMemorySize, SMEM1);
    cudaFuncSetAttribute(attn_kernel, cudaFuncAttributeMaxDynamicSharedMemorySize, SMEM_AT);

    qkv_kernel<<<128, 512, SMEM1>>>(x, Wq_w, Wq_b, Wk_w, Wk_b, Wv_w, Wv_b);
    attn_kernel<<<dim3(SS, BB), 1024, SMEM_AT>>>(tags, mk, ctx, p);
}

// round 13
// speedup vs baseline: 1.2194x; 1.2194x over previous
#include <cuda_runtime.h>
#include <cuda_fp16.h>

#define BB 8
#define SS 16
#define TT 128
#define DD 64
#define NN 2048
#define P0  (0.00048828125f)   // 1/2048

typedef unsigned long long ull;
typedef unsigned int uint;

// fp16 split operands
__device__ __half g_qh[BB*NN*DD], g_ql[BB*NN*DD];
__device__ __half g_kh[BB*NN*DD], g_kl[BB*NN*DD];
__device__ __half g_vph[BB*NN*DD];            // [b][m][d] single fp16, m = t*16+s

__device__ __forceinline__ ull pk2(float x, float y){
    ull r; asm("mov.b64 %0, {%1, %2};" : "=l"(r) : "f"(x), "f"(y)); return r;
}
__device__ __forceinline__ void fma2(ull &d, ull a, ull b){
    asm("fma.rn.f32x2 %0, %1, %2, %0;" : "+l"(d) : "l"(a), "l"(b));
}
__device__ __forceinline__ float2 upk2(ull v){
    float2 r; asm("mov.b64 {%0, %1}, %2;" : "=f"(r.x), "=f"(r.y) : "l"(v)); return r;
}

// ---------------- kernel 1: QKV projection -> fp16 splits (1 wave) ----------------
__global__ void __launch_bounds__(512)
qkv_kernel(const float* __restrict__ x,
           const float* __restrict__ Wq_w, const float* __restrict__ Wq_b,
           const float* __restrict__ Wk_w, const float* __restrict__ Wk_b,
           const float* __restrict__ Wv_w, const float* __restrict__ Wv_b)
{
    extern __shared__ float sm1[];
    float* xs = sm1;               // [128][68]
    float* wt = xs + 128*68;       // [3][64][68]
    float* bs = wt + 3*64*68;      // [3][64]

    int tid = threadIdx.x;
    int r0  = blockIdx.x * 128;

    for (int idx = tid; idx < 64*64; idx += 512) {
        int c = idx >> 6, kk = idx & 63;
        wt[(0*64 + kk)*68 + c] = Wq_w[idx];
        wt[(1*64 + kk)*68 + c] = Wk_w[idx];
        wt[(2*64 + kk)*68 + c] = Wv_w[idx];
    }
    if (tid < 64) {
        bs[tid]       = Wq_b[tid];
        bs[64 + tid]  = Wk_b[tid];
        bs[128 + tid] = Wv_b[tid];
    }
    #pragma unroll
    for (int it = 0; it < 4; it++) {
        int idx = tid + (it << 9);
        int r = idx >> 4, f = idx & 15;
        float4 v = *(const float4*)(x + (size_t)(r0 + r)*64 + (f << 2));
        *(float4*)&xs[r*68 + (f << 2)] = v;
    }
    __syncthreads();

    int cg   = tid & 7;
    int rg   = tid >> 3;
    int row0 = rg << 1;
    const float* x0p = &xs[row0 * 68];
    const float* x1p = x0p + 68;
    int gr0 = r0 + row0;
    int b_  = gr0 >> 11;

    for (int mat = 0; mat < 3; mat++) {
        ull a0[4], a1[4];
        {
            const ulonglong2* bp = (const ulonglong2*)(bs + mat*64 + 8*cg);
            ulonglong2 b01 = bp[0], b23 = bp[1];
            a0[0]=b01.x; a0[1]=b01.y; a0[2]=b23.x; a0[3]=b23.y;
            a1[0]=b01.x; a1[1]=b01.y; a1[2]=b23.x; a1[3]=b23.y;
        }
        const float* wp = &wt[mat*64*68 + 8*cg];
        #pragma unroll 4
        for (int kk = 0; kk < 64; kk++) {
            float q0 = x0p[kk], q1 = x1p[kk];
            ull q0p = pk2(q0, q0), q1p = pk2(q1, q1);
            ulonglong2 w01 = *(const ulonglong2*)(wp + kk*68);
            ulonglong2 w23 = *(const ulonglong2*)(wp + kk*68 + 4);
            fma2(a0[0], q0p, w01.x); fma2(a0[1], q0p, w01.y);
            fma2(a0[2], q0p, w23.x); fma2(a0[3], q0p, w23.y);
            fma2(a1[0], q1p, w01.x); fma2(a1[1], q1p, w01.y);
            fma2(a1[2], q1p, w23.x); fma2(a1[3], q1p, w23.y);
        }
        #pragma unroll
        for (int rr = 0; rr < 2; rr++) {
            int gr = gr0 + rr;
            ull* ap = rr ? a1 : a0;
            float f[8];
            { float2 u0=upk2(ap[0]),u1=upk2(ap[1]),u2=upk2(ap[2]),u3=upk2(ap[3]);
              f[0]=u0.x; f[1]=u0.y; f[2]=u1.x; f[3]=u1.y;
              f[4]=u2.x; f[5]=u2.y; f[6]=u3.x; f[7]=u3.y; }
            __half h[8], lo[8];
            #pragma unroll
            for (int i = 0; i < 8; i++) {
                h[i]  = __float2half_rn(f[i]);
                lo[i] = __float2half_rn(f[i] - __half2float(h[i]));
            }
            if (mat < 2) {
                __half* dh = (mat == 0) ? g_qh : g_kh;
                __half* dl = (mat == 0) ? g_ql : g_kl;
                *(uint4*)(dh + (size_t)gr*64 + 8*cg) = *(uint4*)h;
                *(uint4*)(dl + (size_t)gr*64 + 8*cg) = *(uint4*)lo;
            } else {
                int n = gr & 2047;
                int s_ = n >> 7, t_ = n & 127;
                int m  = t_*16 + s_;
                *(uint4*)(g_vph + ((size_t)(b_ << 11) + m)*64 + 8*cg) = *(uint4*)h;
            }
        }
    }
}

// ---------------- attention (512 threads, fp16, single-sync pipeline) ----------------
#define OFF_QH 0
#define OFF_QL 16384
#define OFF_K0 32768
#define OFF_K0L 49152
#define OFF_K1 65536
#define OFF_K1L 81920
#define OFF_V0 98304
#define OFF_V1 114688
#define OFF_V2 131072
#define OFF_P0 147456
#define OFF_P1 180224
#define OFF_MSB  212992
#define OFF_STLP 215040
#define OFF_UF   216064
#define OFF_FLAG 216576
#define OFF_TAGS 216580
#define SMEM_AT  216704

#define QOFF(r,c) ((uint)((r)*128 + (((c) ^ ((r)&7)) << 4)))
#define VOFF(r,c) ((uint)((r)*256 + (((c) ^ ((r)&7)) << 4)))

__device__ __forceinline__ uint smem_u32(const void* p){
    uint a; asm("{ .reg .u64 t; cvta.to.shared.u64 t, %1; cvt.u32.u64 %0, t; }" : "=r"(a) : "l"(p));
    return a;
}
__device__ __forceinline__ void cpa16(uint dst, const void* src){
    asm volatile("cp.async.cg.shared.global [%0], [%1], 16;"
        :: "r"(dst), "l"(__cvta_generic_to_global(src)) : "memory");
}
#define CPA_COMMIT() asm volatile("cp.async.commit_group;" ::: "memory")
#define CPA_WAIT0()  asm volatile("cp.async.wait_group 0;" ::: "memory")

__device__ __forceinline__ uint4 ldsm4(uint addr){
    uint4 r;
    asm volatile("ldmatrix.sync.aligned.m8n8.x4.shared.b16 {%0,%1,%2,%3}, [%4];"
        : "=r"(r.x), "=r"(r.y), "=r"(r.z), "=r"(r.w) : "r"(addr));
    return r;
}
__device__ __forceinline__ uint4 ldsm4t(uint addr){
    uint4 r;
    asm volatile("ldmatrix.sync.aligned.m8n8.x4.trans.shared.b16 {%0,%1,%2,%3}, [%4];"
        : "=r"(r.x), "=r"(r.y), "=r"(r.z), "=r"(r.w) : "r"(addr));
    return r;
}
__device__ __forceinline__ void mma16816(float* d, uint4 a, uint b0, uint b1){
    asm volatile("mma.sync.aligned.m16n8k16.row.col.f32.f16.f16.f32 "
        "{%0,%1,%2,%3}, {%4,%5,%6,%7}, {%8,%9}, {%0,%1,%2,%3};"
        : "+f"(d[0]), "+f"(d[1]), "+f"(d[2]), "+f"(d[3])
        : "r"(a.x), "r"(a.y), "r"(a.z), "r"(a.w), "r"(b0), "r"(b1));
}

__global__ void __launch_bounds__(512, 1)
attn_kernel(const int* __restrict__ tags, const float* __restrict__ mask,
            float* __restrict__ ctx, float* __restrict__ p)
{
    extern __shared__ char smem[];
    uint sb = smem_u32(smem);
    int tid  = threadIdx.x;
    int wid  = tid >> 5, lane = tid & 31;
    int wr   = wid >> 1;
    int wh   = wid & 1;
    int m0   = wr << 4;
    int nb   = wh << 6;
    int db   = wh << 5;
    int s    = blockIdx.x;
    int b    = blockIdx.y;
    int lq   = lane & 3;
    int lr   = lane >> 2;
    int rA   = m0 + lr, rB = rA + 8;

    int*   tgs  = (int*)(smem + OFF_TAGS);
    uint*  msb  = (uint*)(smem + OFF_MSB);
    float* stlp = (float*)(smem + OFF_STLP);
    int*   ufr  = (int*)(smem + OFF_UF);
    int*   flg  = (int*)(smem + OFF_FLAG);

    if (tid < 16) tgs[tid] = tags[b*16 + tid];
    if (tid == 0) flg[0] = 0;
    {
        int tt = tid >> 2, w = tid & 3;
        uint bits = 0;
        #pragma unroll 8
        for (int j = 0; j < 32; j++)
            bits |= (mask[(size_t)tt*128 + w*32 + j] != 0.f ? 1u : 0u) << j;
        msb[tid] = bits;
    }
    // stage Q hi+lo
    #pragma unroll
    for (int it = 0; it < 2; it++) {
        int idx = tid + (it << 9);
        int r = idx >> 3, c = idx & 7;
        size_t se = ((size_t)((b << 11) + (s << 7) + r))*64 + c*8;
        cpa16(sb + OFF_QH + QOFF(r, c), g_qh + se);
        cpa16(sb + OFF_QL + QOFF(r, c), g_ql + se);
    }
    CPA_COMMIT();
    __syncthreads();

    int mytag = tgs[s];
    uint vmask = 0;
    #pragma unroll
    for (int s2 = 0; s2 < 16; s2++) if (tgs[s2] == mytag) vmask |= 1u << s2;
    int vlist[16], nv = 0;
    #pragma unroll
    for (int s2 = 0; s2 < 16; s2++) if ((vmask >> s2) & 1) vlist[nv++] = s2;

    uint mbA = 0, mbB = 0;
    #pragma unroll
    for (int f = 0; f < 8; f++)
        #pragma unroll
        for (int u = 0; u < 2; u++) {
            int cw = nb + 8*f + 2*lq + u;
            mbA |= ((msb[rA*4 + (cw >> 5)] >> (cw & 31)) & 1u) << (f*2 + u);
            mbB |= ((msb[rB*4 + (cw >> 5)] >> (cw & 31)) & 1u) << (f*2 + u);
        }

    int aRow = m0 + (lane & 7) + ((lane >> 3) & 1)*8;
    int aChS = (lane >> 4);
    int bRowOff = (lane & 7) + ((lane >= 16) ? 8 : 0);
    int bChS = ((lane >> 3) & 1);
    int vRowOff = (lane & 7) + (((lane >> 3) & 1) << 3);
    int vChS = (lane >> 4);

    const __half* gb_kh = g_kh + ((size_t)b << 17);
    const __half* gb_kl = g_kl + ((size_t)b << 17);
    const __half* gb_vh = g_vph + ((size_t)b << 17);

    // ================ pass 1: l = sum exp(s), hi-only QK ================
    float lsA = 0.f, lsB = 0.f;
    {
        #pragma unroll
        for (int it = 0; it < 2; it++) {
            int idx = tid + (it << 9);
            int r = idx >> 3, c = idx & 7;
            cpa16(sb + OFF_K0 + QOFF(r, c), gb_kh + ((size_t)((vlist[0] << 7) + r))*64 + c*8);
        }
        CPA_COMMIT();
        for (int vi = 0; vi < nv; vi++) {
            CPA_WAIT0();
            __syncthreads();
            if (vi + 1 < nv) {
                uint dsto = ((vi + 1) & 1) ? OFF_K1 : OFF_K0;
                #pragma unroll
                for (int it = 0; it < 2; it++) {
                    int idx = tid + (it << 9);
                    int r = idx >> 3, c = idx & 7;
                    cpa16(sb + dsto + QOFF(r, c), gb_kh + ((size_t)((vlist[vi+1] << 7) + r))*64 + c*8);
                }
                CPA_COMMIT();
            }
            uint kb = sb + ((vi & 1) ? OFF_K1 : OFF_K0);
            float acc[8][4];
            #pragma unroll
            for (int f = 0; f < 8; f++) { acc[f][0]=0; acc[f][1]=0; acc[f][2]=0; acc[f][3]=0; }
            #pragma unroll
            for (int ks = 0; ks < 4; ks++) {
                uint4 Ah = ldsm4(sb + OFF_QH + QOFF(aRow, 2*ks + aChS));
                #pragma unroll
                for (int fp = 0; fp < 4; fp++) {
                    int n = nb + 16*fp;
                    uint4 Bv = ldsm4(kb + QOFF(n + bRowOff, 2*ks + bChS));
                    mma16816(acc[2*fp],     Ah, Bv.x, Bv.y);
                    mma16816(acc[2*fp + 1], Ah, Bv.z, Bv.w);
                }
            }
            #pragma unroll
            for (int f = 0; f < 8; f++) {
                lsA += (((mbA >> (2*f)) & 1)   ? __expf(acc[f][0]*0.125f) : 0.f)
                     + (((mbA >> (2*f+1)) & 1) ? __expf(acc[f][1]*0.125f) : 0.f);
                lsB += (((mbB >> (2*f)) & 1)   ? __expf(acc[f][2]*0.125f) : 0.f)
                     + (((mbB >> (2*f+1)) & 1) ? __expf(acc[f][3]*0.125f) : 0.f);
            }
        }
    }
    // prefetch pass-2 block 0 (K hi+lo, V) while reducing
    #pragma unroll
    for (int it = 0; it < 2; it++) {
        int idx = tid + (it << 9);
        int r = idx >> 3, c = idx & 7;
        size_t se = ((size_t)((vlist[0] << 7) + r))*64 + c*8;
        cpa16(sb + OFF_K0  + QOFF(r, c), gb_kh + se);
        cpa16(sb + OFF_K0L + QOFF(r, c), gb_kl + se);
        cpa16(sb + OFF_V0  + QOFF(r, c), gb_vh + se);
    }
    CPA_COMMIT();

    lsA += __shfl_xor_sync(0xffffffffu, lsA, 1);
    lsA += __shfl_xor_sync(0xffffffffu, lsA, 2);
    lsB += __shfl_xor_sync(0xffffffffu, lsB, 1);
    lsB += __shfl_xor_sync(0xffffffffu, lsB, 2);
    __syncthreads();
    if (lq == 0) { stlp[rA*2 + wh] = lsA; stlp[rB*2 + wh] = lsB; }
    __syncthreads();
    float lA = stlp[rA*2] + stlp[rA*2+1];
    float lB = stlp[rB*2] + stlp[rB*2+1];
    int ufA = (lA == 0.f), ufB = (lB == 0.f);
    float invlA = ufA ? 0.f : 1.f/lA;
    float invlB = ufB ? 0.f : 1.f/lB;
    if (lq == 0 && wh == 0) { ufr[rA] = ufA; ufr[rB] = ufB; if (ufA | ufB) flg[0] = 1; }
    __syncthreads();
    int anyU = flg[0];
    if (anyU) {
        // restage block 0 (index order changes to 0..15)
        #pragma unroll
        for (int it = 0; it < 2; it++) {
            int idx = tid + (it << 9);
            int r = idx >> 3, c = idx & 7;
            size_t se = ((size_t)r)*64 + c*8;
            cpa16(sb + OFF_K0  + QOFF(r, c), gb_kh + se);
            cpa16(sb + OFF_K0L + QOFF(r, c), gb_kl + se);
            cpa16(sb + OFF_V0  + QOFF(r, c), gb_vh + se);
        }
        CPA_COMMIT();
    }

    // ================ pass 2: single sync per block, deferred AV ================
    int nproc = anyU ? 16 : nv;
    float accAV[4][4];
    #pragma unroll
    for (int f = 0; f < 4; f++) { accAV[f][0]=0; accAV[f][1]=0; accAV[f][2]=0; accAV[f][3]=0; }
    float* pbase = p + ((size_t)(b*2048 + s*128))*2048;
    const uint voffs0 = OFF_V0, voffs1 = OFF_V1, voffs2 = OFF_V2;

    for (int i = 0; i < nproc; i++) {
        int s2 = anyU ? i : vlist[i];
        int bv = (vmask >> s2) & 1;
        CPA_WAIT0();
        __syncthreads();   // K(i),V(i) ready; P(i-1) visible
        // deferred AV on block i-1
        if (i > 0) {
            uint pb2 = sb + (((i-1) & 1) ? OFF_P1 : OFF_P0);
            int vm3 = (i-1) % 3;
            uint vb2 = sb + (vm3 == 0 ? voffs0 : (vm3 == 1 ? voffs1 : voffs2));
            #pragma unroll
            for (int ks = 0; ks < 8; ks++) {
                uint4 Ah = ldsm4(pb2 + VOFF(aRow, 2*ks + aChS));
                #pragma unroll
                for (int fp = 0; fp < 2; fp++) {
                    int cch = ((db + 16*fp) >> 3) + vChS;
                    uint4 Bh = ldsm4t(vb2 + QOFF(16*ks + vRowOff, cch));
                    mma16816(accAV[2*fp],     Ah, Bh.x, Bh.y);
                    mma16816(accAV[2*fp + 1], Ah, Bh.z, Bh.w);
                }
            }
        }
        // prefetch block i+1
        if (i + 1 < nproc) {
            int s3 = anyU ? (i + 1) : vlist[i + 1];
            uint dh = ((i + 1) & 1) ? OFF_K1 : OFF_K0;
            uint dl = ((i + 1) & 1) ? OFF_K1L : OFF_K0L;
            int vn3 = (i + 1) % 3;
            uint dv = (vn3 == 0 ? voffs0 : (vn3 == 1 ? voffs1 : voffs2));
            #pragma unroll
            for (int it = 0; it < 2; it++) {
                int idx = tid + (it << 9);
                int r = idx >> 3, c = idx & 7;
                size_t se = ((size_t)((s3 << 7) + r))*64 + c*8;
                cpa16(sb + dh + QOFF(r, c), gb_kh + se);
                cpa16(sb + dl + QOFF(r, c), gb_kl + se);
                cpa16(sb + dv + QOFF(r, c), gb_vh + se);
            }
            CPA_COMMIT();
        }
        uint kbh = sb + ((i & 1) ? OFF_K1 : OFF_K0);
        uint kbl = sb + ((i & 1) ? OFF_K1L : OFF_K0L);
        uint pcur = sb + ((i & 1) ? OFF_P1 : OFF_P0);
        if (bv) {
            float acc[8][4];
            #pragma unroll
            for (int f = 0; f < 8; f++) { acc[f][0]=0; acc[f][1]=0; acc[f][2]=0; acc[f][3]=0; }
            #pragma unroll
            for (int ks = 0; ks < 4; ks++) {
                uint4 Ah = ldsm4(sb + OFF_QH + QOFF(aRow, 2*ks + aChS));
                uint4 Al = ldsm4(sb + OFF_QL + QOFF(aRow, 2*ks + aChS));
                #pragma unroll
                for (int fp = 0; fp < 4; fp++) {
                    int n = nb + 16*fp;
                    uint4 Bh = ldsm4(kbh + QOFF(n + bRowOff, 2*ks + bChS));
                    mma16816(acc[2*fp],     Ah, Bh.x, Bh.y);
                    mma16816(acc[2*fp + 1], Ah, Bh.z, Bh.w);
                    mma16816(acc[2*fp],     Al, Bh.x, Bh.y);
                    mma16816(acc[2*fp + 1], Al, Bh.z, Bh.w);
                    uint4 Bl = ldsm4(kbl + QOFF(n + bRowOff, 2*ks + bChS));
                    mma16816(acc[2*fp],     Ah, Bl.x, Bl.y);
                    mma16816(acc[2*fp + 1], Ah, Bl.z, Bl.w);
                }
            }
            #pragma unroll
            for (int f = 0; f < 8; f++) {
                float e0 = ((mbA >> (2*f)) & 1)   ? __expf(acc[f][0]*0.125f) : 0.f;
                float e1 = ((mbA >> (2*f+1)) & 1) ? __expf(acc[f][1]*0.125f) : 0.f;
                float e2 = ((mbB >> (2*f)) & 1)   ? __expf(acc[f][2]*0.125f) : 0.f;
                float e3 = ((mbB >> (2*f+1)) & 1) ? __expf(acc[f][3]*0.125f) : 0.f;
                float p0 = ufA ? P0 : e0*invlA;
                float p1 = ufA ? P0 : e1*invlA;
                float p2 = ufB ? P0 : e2*invlB;
                float p3 = ufB ? P0 : e3*invlB;
                int cw = nb + 8*f + 2*lq;
                *(float2*)(pbase + (size_t)rA*2048 + s2*128 + cw) = make_float2(p0, p1);
                *(float2*)(pbase + (size_t)rB*2048 + s2*128 + cw) = make_float2(p2, p3);
                int ch = (wh << 3) + f;
                __half2 hA = __floats2half2_rn(p0, p1);
                __half2 hB = __floats2half2_rn(p2, p3);
                *(uint*)(smem + (pcur - sb) + VOFF(rA, ch) + 4*lq) = *(uint*)&hA;
                *(uint*)(smem + (pcur - sb) + VOFF(rB, ch) + 4*lq) = *(uint*)&hB;
            }
        } else {
            for (int i2 = tid; i2 < 2048; i2 += 512) {
                int r = i2 >> 4, c = i2 & 15;
                float pv = ufr[r] ? P0 : 0.f;
                __half2 hv2 = __floats2half2_rn(pv, pv);
                uint hw = *(uint*)&hv2;
                uint4 hv; hv.x = hv.y = hv.z = hv.w = hw;
                *(uint4*)(smem + (pcur - sb) + VOFF(r, c)) = hv;
            }
            for (int i2 = tid; i2 < 4096; i2 += 512) {
                int r = i2 >> 5, c4 = i2 & 31;
                float pv = ufr[r] ? P0 : 0.f;
                *(float4*)(pbase + (size_t)r*2048 + s2*128 + (c4 << 2)) =
                    make_float4(pv, pv, pv, pv);
            }
        }
    }
    // epilogue AV on last block
    __syncthreads();
    {
        int il = nproc - 1;
        uint pb2 = sb + ((il & 1) ? OFF_P1 : OFF_P0);
        int vm3 = il % 3;
        uint vb2 = sb + (vm3 == 0 ? voffs0 : (vm3 == 1 ? voffs1 : voffs2));
        #pragma unroll
        for (int ks = 0; ks < 8; ks++) {
            uint4 Ah = ldsm4(pb2 + VOFF(aRow, 2*ks + aChS));
            #pragma unroll
            for (int fp = 0; fp < 2; fp++) {
                int cch = ((db + 16*fp) >> 3) + vChS;
                uint4 Bh = ldsm4t(vb2 + QOFF(16*ks + vRowOff, cch));
                mma16816(accAV[2*fp],     Ah, Bh.x, Bh.y);
                mma16816(accAV[2*fp + 1], Ah, Bh.z, Bh.w);
            }
        }
    }

    if (!anyU) {
        for (int s2 = 0; s2 < 16; s2++) {
            if ((vmask >> s2) & 1) continue;
            float4 z = make_float4(0.f, 0.f, 0.f, 0.f);
            for (int i2 = tid; i2 < 4096; i2 += 512) {
                int r = i2 >> 5, c4 = i2 & 31;
                *(float4*)(pbase + (size_t)r*2048 + s2*128 + (c4 << 2)) = z;
            }
        }
    }

    {
        float* cb = ctx + ((size_t)(b*2048 + s*128))*64;
        #pragma unroll
        for (int f = 0; f < 2; f++) {
            int dc = db + 8*f + 2*lq;
            *(float2*)(cb + (size_t)rA*64 + dc) = make_float2(accAV[f][0], accAV[f][1]);
            *(float2*)(cb + (size_t)rB*64 + dc) = make_float2(accAV[f][2], accAV[f][3]);
        }
        #pragma unroll
        for (int f = 2; f < 4; f++) {
            int dc = db + 8*(f-2) + 16 + 2*lq;
            *(float2*)(cb + (size_t)rA*64 + dc) = make_float2(accAV[f][0], accAV[f][1]);
            *(float2*)(cb + (size_t)rB*64 + dc) = make_float2(accAV[f][2], accAV[f][3]);
        }
    }
}

#define SMEM1 ((128*68 + 3*64*68 + 3*64) * 4)

extern "C" void kernel_launch(void* const* d_in, const int* in_sizes, int n_in,
                              void* d_out, int out_size) {
    const float* x    = (const float*)d_in[0];
    const int*   tags = (const int*)  d_in[1];
    const float* mk   = (const float*)d_in[2];
    const float* Wk_w = (const float*)d_in[3];
    const float* Wk_b = (const float*)d_in[4];
    const float* Wq_w = (const float*)d_in[5];
    const float* Wq_b = (const float*)d_in[6];
    const float* Wv_w = (const float*)d_in[7];
    const float* Wv_b = (const float*)d_in[8];

    float* ctx = (float*)d_out;                        // [8,16,128,64]
    float* p   = ctx + (size_t)BB*SS*TT*DD;            // [8,2048,2048]

    cudaFuncSetAttribute(qkv_kernel,  cudaFuncAttributeMaxDynamicSharedMemorySize, SMEM1);
    cudaFuncSetAttribute(attn_kernel, cudaFuncAttributeMaxDynamicSharedMemorySize, SMEM_AT);

    qkv_kernel<<<128, 512, SMEM1>>>(x, Wq_w, Wq_b, Wk_w, Wk_b, Wv_w, Wv_b);
    attn_kernel<<<dim3(SS, BB), 512, SMEM_AT>>>(tags, mk, ctx, p);
}

// round 15
// speedup vs baseline: 1.5322x; 1.2565x over previous
#include <cuda_runtime.h>
#include <cuda_fp16.h>

#define BB 8
#define SS 16
#define TT 128
#define DD 64
#define NN 2048
#define P0  (0.00048828125f)   // 1/2048

typedef unsigned long long ull;
typedef unsigned int uint;

// fp16 split operands
__device__ __half g_qh[BB*NN*DD], g_ql[BB*NN*DD];
__device__ __half g_kh[BB*NN*DD], g_kl[BB*NN*DD];
__device__ __half g_vph[BB*NN*DD];            // [b][m][d] single fp16, m = t*16+s

#define QOFF(r,c) ((uint)((r)*128 + (((c) ^ ((r)&7)) << 4)))
#define VOFF(r,c) ((uint)((r)*256 + (((c) ^ ((r)&7)) << 4)))

__device__ __forceinline__ uint smem_u32(const void* p){
    uint a; asm("{ .reg .u64 t; cvta.to.shared.u64 t, %1; cvt.u32.u64 %0, t; }" : "=r"(a) : "l"(p));
    return a;
}
__device__ __forceinline__ void cpa16(uint dst, const void* src){
    asm volatile("cp.async.cg.shared.global [%0], [%1], 16;"
        :: "r"(dst), "l"(__cvta_generic_to_global(src)) : "memory");
}
#define CPA_COMMIT() asm volatile("cp.async.commit_group;" ::: "memory")
#define CPA_WAIT0()  asm volatile("cp.async.wait_group 0;" ::: "memory")

__device__ __forceinline__ uint4 ldsm4(uint addr){
    uint4 r;
    asm volatile("ldmatrix.sync.aligned.m8n8.x4.shared.b16 {%0,%1,%2,%3}, [%4];"
        : "=r"(r.x), "=r"(r.y), "=r"(r.z), "=r"(r.w) : "r"(addr));
    return r;
}
__device__ __forceinline__ uint4 ldsm4t(uint addr){
    uint4 r;
    asm volatile("ldmatrix.sync.aligned.m8n8.x4.trans.shared.b16 {%0,%1,%2,%3}, [%4];"
        : "=r"(r.x), "=r"(r.y), "=r"(r.z), "=r"(r.w) : "r"(addr));
    return r;
}
__device__ __forceinline__ void mma16816(float* d, uint4 a, uint b0, uint b1){
    asm volatile("mma.sync.aligned.m16n8k16.row.col.f32.f16.f16.f32 "
        "{%0,%1,%2,%3}, {%4,%5,%6,%7}, {%8,%9}, {%0,%1,%2,%3};"
        : "+f"(d[0]), "+f"(d[1]), "+f"(d[2]), "+f"(d[3])
        : "r"(a.x), "r"(a.y), "r"(a.z), "r"(a.w), "r"(b0), "r"(b1));
}

// ---------------- kernel 1: QKV projection via mma.sync ----------------
// CTA = 128 rows = one (b, s). A = x (fp16 split), B = [Wq|Wk|Wv] (fp16 split).
#define QK_XH 0
#define QK_XL 16384
#define QK_WH 32768          // 192 rows x 128 B = 24576
#define QK_WL 57344
#define QK_BS 81920          // 192 floats
#define SMEM_QKV 82944

__global__ void __launch_bounds__(512)
qkv_kernel(const float* __restrict__ x,
           const float* __restrict__ Wq_w, const float* __restrict__ Wq_b,
           const float* __restrict__ Wk_w, const float* __restrict__ Wk_b,
           const float* __restrict__ Wv_w, const float* __restrict__ Wv_b)
{
    extern __shared__ char smq[];
    uint sb = smem_u32(smq);
    float* bs = (float*)(smq + QK_BS);
    int tid = threadIdx.x;
    int gr0 = blockIdx.x * 128;
    int b_  = blockIdx.x >> 4;
    int s_  = blockIdx.x & 15;

    // stage x -> fp16 split (swizzled)
    #pragma unroll
    for (int it = 0; it < 2; it++) {
        int idx = tid + (it << 9);
        int r = idx >> 3, c = idx & 7;
        const float* src = x + (size_t)(gr0 + r)*64 + c*8;
        float4 v0 = *(const float4*)src;
        float4 v1 = *(const float4*)(src + 4);
        float f[8] = {v0.x,v0.y,v0.z,v0.w,v1.x,v1.y,v1.z,v1.w};
        __half h[8], lo[8];
        #pragma unroll
        for (int i = 0; i < 8; i++) {
            h[i]  = __float2half_rn(f[i]);
            lo[i] = __float2half_rn(f[i] - __half2float(h[i]));
        }
        *(uint4*)(smq + QK_XH + QOFF(r, c)) = *(uint4*)h;
        *(uint4*)(smq + QK_XL + QOFF(r, c)) = *(uint4*)lo;
    }
    // stage W (3 x 64 x 64) -> fp16 split, rows n = mat*64 + outcol
    #pragma unroll
    for (int it = 0; it < 3; it++) {
        int idx = tid + it*512;
        int n = idx >> 3, c = idx & 7;
        const float* wsrc = (n < 64) ? Wq_w : ((n < 128) ? Wk_w : Wv_w);
        const float* src = wsrc + (size_t)(n & 63)*64 + c*8;
        float4 v0 = *(const float4*)src;
        float4 v1 = *(const float4*)(src + 4);
        float f[8] = {v0.x,v0.y,v0.z,v0.w,v1.x,v1.y,v1.z,v1.w};
        __half h[8], lo[8];
        #pragma unroll
        for (int i = 0; i < 8; i++) {
            h[i]  = __float2half_rn(f[i]);
            lo[i] = __float2half_rn(f[i] - __half2float(h[i]));
        }
        *(uint4*)(smq + QK_WH + QOFF(n, c)) = *(uint4*)h;
        *(uint4*)(smq + QK_WL + QOFF(n, c)) = *(uint4*)lo;
    }
    if (tid < 192)
        bs[tid] = (tid < 64) ? Wq_b[tid] : ((tid < 128) ? Wk_b[tid-64] : Wv_b[tid-128]);
    __syncthreads();

    int wid  = tid >> 5, lane = tid & 31;
    int wr   = wid >> 1;
    int wh   = wid & 1;
    int m0   = wr << 4;
    int nb   = wh * 96;
    int lq   = lane & 3;
    int lr   = lane >> 2;
    int rA   = m0 + lr, rB = rA + 8;
    int aRow = m0 + (lane & 7) + ((lane >> 3) & 1)*8;
    int aChS = (lane >> 4);
    int bRowOff = (lane & 7) + ((lane >= 16) ? 8 : 0);
    int bChS = ((lane >> 3) & 1);

    float acc[12][4];
    #pragma unroll
    for (int f = 0; f < 12; f++) { acc[f][0]=0; acc[f][1]=0; acc[f][2]=0; acc[f][3]=0; }

    #pragma unroll
    for (int ks = 0; ks < 4; ks++) {
        uint4 Ah = ldsm4(sb + QK_XH + QOFF(aRow, 2*ks + aChS));
        uint4 Al = ldsm4(sb + QK_XL + QOFF(aRow, 2*ks + aChS));
        #pragma unroll
        for (int fp = 0; fp < 6; fp++) {
            int n = nb + 16*fp;
            uint4 Bh = ldsm4(sb + QK_WH + QOFF(n + bRowOff, 2*ks + bChS));
            mma16816(acc[2*fp],     Ah, Bh.x, Bh.y);
            mma16816(acc[2*fp + 1], Ah, Bh.z, Bh.w);
            mma16816(acc[2*fp],     Al, Bh.x, Bh.y);
            mma16816(acc[2*fp + 1], Al, Bh.z, Bh.w);
            uint4 Bl = ldsm4(sb + QK_WL + QOFF(n + bRowOff, 2*ks + bChS));
            mma16816(acc[2*fp],     Ah, Bl.x, Bl.y);
            mma16816(acc[2*fp + 1], Ah, Bl.z, Bl.w);
        }
    }

    // epilogue: add bias, split, store
    #pragma unroll
    for (int f = 0; f < 12; f++) {
        int col0 = nb + 8*f + 2*lq;
        int mat  = col0 >> 6;
        int cc   = col0 & 63;
        float b0 = bs[col0], b1 = bs[col0 + 1];
        float vA0 = acc[f][0] + b0, vA1 = acc[f][1] + b1;
        float vB0 = acc[f][2] + b0, vB1 = acc[f][3] + b1;
        __half hA0 = __float2half_rn(vA0), hA1 = __float2half_rn(vA1);
        __half hB0 = __float2half_rn(vB0), hB1 = __float2half_rn(vB1);
        if (mat < 2) {
            __half* dh = mat ? g_kh : g_qh;
            __half* dl = mat ? g_kl : g_ql;
            __half2 hA(hA0, hA1), hB(hB0, hB1);
            __half2 lA(__float2half_rn(vA0 - __half2float(hA0)),
                       __float2half_rn(vA1 - __half2float(hA1)));
            __half2 lB(__float2half_rn(vB0 - __half2float(hB0)),
                       __float2half_rn(vB1 - __half2float(hB1)));
            *(uint*)(dh + (size_t)(gr0 + rA)*64 + cc) = *(uint*)&hA;
            *(uint*)(dh + (size_t)(gr0 + rB)*64 + cc) = *(uint*)&hB;
            *(uint*)(dl + (size_t)(gr0 + rA)*64 + cc) = *(uint*)&lA;
            *(uint*)(dl + (size_t)(gr0 + rB)*64 + cc) = *(uint*)&lB;
        } else {
            int mA = rA*16 + s_, mB = rB*16 + s_;
            __half2 hA(hA0, hA1), hB(hB0, hB1);
            *(uint*)(g_vph + ((size_t)(b_ << 11) + mA)*64 + cc) = *(uint*)&hA;
            *(uint*)(g_vph + ((size_t)(b_ << 11) + mB)*64 + cc) = *(uint*)&hB;
        }
    }
}

// ---------------- attention (512 threads, fp16, single-sync pipeline) ----------------
#define OFF_QH 0
#define OFF_QL 16384
#define OFF_K0 32768
#define OFF_K0L 49152
#define OFF_K1 65536
#define OFF_K1L 81920
#define OFF_V0 98304
#define OFF_V1 114688
#define OFF_V2 131072
#define OFF_P0 147456
#define OFF_P1 180224
#define OFF_MSB  212992
#define OFF_STLP 215040
#define OFF_UF   216064
#define OFF_FLAG 216576
#define OFF_TAGS 216580
#define SMEM_AT  216704

__global__ void __launch_bounds__(512, 1)
attn_kernel(const int* __restrict__ tags, const float* __restrict__ mask,
            float* __restrict__ ctx, float* __restrict__ p)
{
    extern __shared__ char smem[];
    uint sb = smem_u32(smem);
    int tid  = threadIdx.x;
    int wid  = tid >> 5, lane = tid & 31;
    int wr   = wid >> 1;
    int wh   = wid & 1;
    int m0   = wr << 4;
    int nb   = wh << 6;
    int db   = wh << 5;
    int s    = blockIdx.x;
    int b    = blockIdx.y;
    int lq   = lane & 3;
    int lr   = lane >> 2;
    int rA   = m0 + lr, rB = rA + 8;

    int*   tgs  = (int*)(smem + OFF_TAGS);
    uint*  msb  = (uint*)(smem + OFF_MSB);
    float* stlp = (float*)(smem + OFF_STLP);
    int*   ufr  = (int*)(smem + OFF_UF);
    int*   flg  = (int*)(smem + OFF_FLAG);

    if (tid < 16) tgs[tid] = tags[b*16 + tid];
    if (tid == 0) flg[0] = 0;
    {
        int tt = tid >> 2, w = tid & 3;
        uint bits = 0;
        #pragma unroll 8
        for (int j = 0; j < 32; j++)
            bits |= (mask[(size_t)tt*128 + w*32 + j] != 0.f ? 1u : 0u) << j;
        msb[tid] = bits;
    }
    // stage Q hi+lo
    #pragma unroll
    for (int it = 0; it < 2; it++) {
        int idx = tid + (it << 9);
        int r = idx >> 3, c = idx & 7;
        size_t se = ((size_t)((b << 11) + (s << 7) + r))*64 + c*8;
        cpa16(sb + OFF_QH + QOFF(r, c), g_qh + se);
        cpa16(sb + OFF_QL + QOFF(r, c), g_ql + se);
    }
    CPA_COMMIT();
    __syncthreads();

    int mytag = tgs[s];
    uint vmask = 0;
    #pragma unroll
    for (int s2 = 0; s2 < 16; s2++) if (tgs[s2] == mytag) vmask |= 1u << s2;
    int vlist[16], nv = 0;
    #pragma unroll
    for (int s2 = 0; s2 < 16; s2++) if ((vmask >> s2) & 1) vlist[nv++] = s2;

    uint mbA = 0, mbB = 0;
    #pragma unroll
    for (int f = 0; f < 8; f++)
        #pragma unroll
        for (int u = 0; u < 2; u++) {
            int cw = nb + 8*f + 2*lq + u;
            mbA |= ((msb[rA*4 + (cw >> 5)] >> (cw & 31)) & 1u) << (f*2 + u);
            mbB |= ((msb[rB*4 + (cw >> 5)] >> (cw & 31)) & 1u) << (f*2 + u);
        }

    int aRow = m0 + (lane & 7) + ((lane >> 3) & 1)*8;
    int aChS = (lane >> 4);
    int bRowOff = (lane & 7) + ((lane >= 16) ? 8 : 0);
    int bChS = ((lane >> 3) & 1);
    int vRowOff = (lane & 7) + (((lane >> 3) & 1) << 3);
    int vChS = (lane >> 4);

    const __half* gb_kh = g_kh + ((size_t)b << 17);
    const __half* gb_kl = g_kl + ((size_t)b << 17);
    const __half* gb_vh = g_vph + ((size_t)b << 17);

    // ================ pass 1: l = sum exp(s), hi-only QK ================
    float lsA = 0.f, lsB = 0.f;
    {
        #pragma unroll
        for (int it = 0; it < 2; it++) {
            int idx = tid + (it << 9);
            int r = idx >> 3, c = idx & 7;
            cpa16(sb + OFF_K0 + QOFF(r, c), gb_kh + ((size_t)((vlist[0] << 7) + r))*64 + c*8);
        }
        CPA_COMMIT();
        for (int vi = 0; vi < nv; vi++) {
            CPA_WAIT0();
            __syncthreads();
            if (vi + 1 < nv) {
                uint dsto = ((vi + 1) & 1) ? OFF_K1 : OFF_K0;
                #pragma unroll
                for (int it = 0; it < 2; it++) {
                    int idx = tid + (it << 9);
                    int r = idx >> 3, c = idx & 7;
                    cpa16(sb + dsto + QOFF(r, c), gb_kh + ((size_t)((vlist[vi+1] << 7) + r))*64 + c*8);
                }
                CPA_COMMIT();
            }
            uint kb = sb + ((vi & 1) ? OFF_K1 : OFF_K0);
            float acc[8][4];
            #pragma unroll
            for (int f = 0; f < 8; f++) { acc[f][0]=0; acc[f][1]=0; acc[f][2]=0; acc[f][3]=0; }
            #pragma unroll
            for (int ks = 0; ks < 4; ks++) {
                uint4 Ah = ldsm4(sb + OFF_QH + QOFF(aRow, 2*ks + aChS));
                #pragma unroll
                for (int fp = 0; fp < 4; fp++) {
                    int n = nb + 16*fp;
                    uint4 Bv = ldsm4(kb + QOFF(n + bRowOff, 2*ks + bChS));
                    mma16816(acc[2*fp],     Ah, Bv.x, Bv.y);
                    mma16816(acc[2*fp + 1], Ah, Bv.z, Bv.w);
                }
            }
            #pragma unroll
            for (int f = 0; f < 8; f++) {
                lsA += (((mbA >> (2*f)) & 1)   ? __expf(acc[f][0]*0.125f) : 0.f)
                     + (((mbA >> (2*f+1)) & 1) ? __expf(acc[f][1]*0.125f) : 0.f);
                lsB += (((mbB >> (2*f)) & 1)   ? __expf(acc[f][2]*0.125f) : 0.f)
                     + (((mbB >> (2*f+1)) & 1) ? __expf(acc[f][3]*0.125f) : 0.f);
            }
        }
    }
    // prefetch pass-2 block 0 (K hi+lo, V) while reducing
    #pragma unroll
    for (int it = 0; it < 2; it++) {
        int idx = tid + (it << 9);
        int r = idx >> 3, c = idx & 7;
        size_t se = ((size_t)((vlist[0] << 7) + r))*64 + c*8;
        cpa16(sb + OFF_K0  + QOFF(r, c), gb_kh + se);
        cpa16(sb + OFF_K0L + QOFF(r, c), gb_kl + se);
        cpa16(sb + OFF_V0  + QOFF(r, c), gb_vh + se);
    }
    CPA_COMMIT();

    lsA += __shfl_xor_sync(0xffffffffu, lsA, 1);
    lsA += __shfl_xor_sync(0xffffffffu, lsA, 2);
    lsB += __shfl_xor_sync(0xffffffffu, lsB, 1);
    lsB += __shfl_xor_sync(0xffffffffu, lsB, 2);
    __syncthreads();
    if (lq == 0) { stlp[rA*2 + wh] = lsA; stlp[rB*2 + wh] = lsB; }
    __syncthreads();
    float lA = stlp[rA*2] + stlp[rA*2+1];
    float lB = stlp[rB*2] + stlp[rB*2+1];
    int ufA = (lA == 0.f), ufB = (lB == 0.f);
    float invlA = ufA ? 0.f : 1.f/lA;
    float invlB = ufB ? 0.f : 1.f/lB;
    if (lq == 0 && wh == 0) { ufr[rA] = ufA; ufr[rB] = ufB; if (ufA | ufB) flg[0] = 1; }
    __syncthreads();
    int anyU = flg[0];
    if (anyU) {
        // restage block 0 (index order changes to 0..15)
        #pragma unroll
        for (int it = 0; it < 2; it++) {
            int idx = tid + (it << 9);
            int r = idx >> 3, c = idx & 7;
            size_t se = ((size_t)r)*64 + c*8;
            cpa16(sb + OFF_K0  + QOFF(r, c), gb_kh + se);
            cpa16(sb + OFF_K0L + QOFF(r, c), gb_kl + se);
            cpa16(sb + OFF_V0  + QOFF(r, c), gb_vh + se);
        }
        CPA_COMMIT();
    }

    // ================ pass 2: single sync per block, deferred AV ================
    int nproc = anyU ? 16 : nv;
    float accAV[4][4];
    #pragma unroll
    for (int f = 0; f < 4; f++) { accAV[f][0]=0; accAV[f][1]=0; accAV[f][2]=0; accAV[f][3]=0; }
    float* pbase = p + ((size_t)(b*2048 + s*128))*2048;
    const uint voffs0 = OFF_V0, voffs1 = OFF_V1, voffs2 = OFF_V2;

    for (int i = 0; i < nproc; i++) {
        int s2 = anyU ? i : vlist[i];
        int bv = (vmask >> s2) & 1;
        CPA_WAIT0();
        __syncthreads();   // K(i),V(i) ready; P(i-1) visible
        // deferred AV on block i-1
        if (i > 0) {
            uint pb2 = sb + (((i-1) & 1) ? OFF_P1 : OFF_P0);
            int vm3 = (i-1) % 3;
            uint vb2 = sb + (vm3 == 0 ? voffs0 : (vm3 == 1 ? voffs1 : voffs2));
            #pragma unroll
            for (int ks = 0; ks < 8; ks++) {
                uint4 Ah = ldsm4(pb2 + VOFF(aRow, 2*ks + aChS));
                #pragma unroll
                for (int fp = 0; fp < 2; fp++) {
                    int cch = ((db + 16*fp) >> 3) + vChS;
                    uint4 Bh = ldsm4t(vb2 + QOFF(16*ks + vRowOff, cch));
                    mma16816(accAV[2*fp],     Ah, Bh.x, Bh.y);
                    mma16816(accAV[2*fp + 1], Ah, Bh.z, Bh.w);
                }
            }
        }
        // prefetch block i+1
        if (i + 1 < nproc) {
            int s3 = anyU ? (i + 1) : vlist[i + 1];
            uint dh = ((i + 1) & 1) ? OFF_K1 : OFF_K0;
            uint dl = ((i + 1) & 1) ? OFF_K1L : OFF_K0L;
            int vn3 = (i + 1) % 3;
            uint dv = (vn3 == 0 ? voffs0 : (vn3 == 1 ? voffs1 : voffs2));
            #pragma unroll
            for (int it = 0; it < 2; it++) {
                int idx = tid + (it << 9);
                int r = idx >> 3, c = idx & 7;
                size_t se = ((size_t)((s3 << 7) + r))*64 + c*8;
                cpa16(sb + dh + QOFF(r, c), gb_kh + se);
                cpa16(sb + dl + QOFF(r, c), gb_kl + se);
                cpa16(sb + dv + QOFF(r, c), gb_vh + se);
            }
            CPA_COMMIT();
        }
        uint kbh = sb + ((i & 1) ? OFF_K1 : OFF_K0);
        uint kbl = sb + ((i & 1) ? OFF_K1L : OFF_K0L);
        uint pcur = sb + ((i & 1) ? OFF_P1 : OFF_P0);
        if (bv) {
            float acc[8][4];
            #pragma unroll
            for (int f = 0; f < 8; f++) { acc[f][0]=0; acc[f][1]=0; acc[f][2]=0; acc[f][3]=0; }
            #pragma unroll
            for (int ks = 0; ks < 4; ks++) {
                uint4 Ah = ldsm4(sb + OFF_QH + QOFF(aRow, 2*ks + aChS));
                uint4 Al = ldsm4(sb + OFF_QL + QOFF(aRow, 2*ks + aChS));
                #pragma unroll
                for (int fp = 0; fp < 4; fp++) {
                    int n = nb + 16*fp;
                    uint4 Bh = ldsm4(kbh + QOFF(n + bRowOff, 2*ks + bChS));
                    mma16816(acc[2*fp],     Ah, Bh.x, Bh.y);
                    mma16816(acc[2*fp + 1], Ah, Bh.z, Bh.w);
                    mma16816(acc[2*fp],     Al, Bh.x, Bh.y);
                    mma16816(acc[2*fp + 1], Al, Bh.z, Bh.w);
                    uint4 Bl = ldsm4(kbl + QOFF(n + bRowOff, 2*ks + bChS));
                    mma16816(acc[2*fp],     Ah, Bl.x, Bl.y);
                    mma16816(acc[2*fp + 1], Ah, Bl.z, Bl.w);
                }
            }
            #pragma unroll
            for (int f = 0; f < 8; f++) {
                float e0 = ((mbA >> (2*f)) & 1)   ? __expf(acc[f][0]*0.125f) : 0.f;
                float e1 = ((mbA >> (2*f+1)) & 1) ? __expf(acc[f][1]*0.125f) : 0.f;
                float e2 = ((mbB >> (2*f)) & 1)   ? __expf(acc[f][2]*0.125f) : 0.f;
                float e3 = ((mbB >> (2*f+1)) & 1) ? __expf(acc[f][3]*0.125f) : 0.f;
                float p0 = ufA ? P0 : e0*invlA;
                float p1 = ufA ? P0 : e1*invlA;
                float p2 = ufB ? P0 : e2*invlB;
                float p3 = ufB ? P0 : e3*invlB;
                int cw = nb + 8*f + 2*lq;
                *(float2*)(pbase + (size_t)rA*2048 + s2*128 + cw) = make_float2(p0, p1);
                *(float2*)(pbase + (size_t)rB*2048 + s2*128 + cw) = make_float2(p2, p3);
                int ch = (wh << 3) + f;
                __half2 hA = __floats2half2_rn(p0, p1);
                __half2 hB = __floats2half2_rn(p2, p3);
                *(uint*)(smem + (pcur - sb) + VOFF(rA, ch) + 4*lq) = *(uint*)&hA;
                *(uint*)(smem + (pcur - sb) + VOFF(rB, ch) + 4*lq) = *(uint*)&hB;
            }
        } else {
            for (int i2 = tid; i2 < 2048; i2 += 512) {
                int r = i2 >> 4, c = i2 & 15;
                float pv = ufr[r] ? P0 : 0.f;
                __half2 hv2 = __floats2half2_rn(pv, pv);
                uint hw = *(uint*)&hv2;
                uint4 hv; hv.x = hv.y = hv.z = hv.w = hw;
                *(uint4*)(smem + (pcur - sb) + VOFF(r, c)) = hv;
            }
            for (int i2 = tid; i2 < 4096; i2 += 512) {
                int r = i2 >> 5, c4 = i2 & 31;
                float pv = ufr[r] ? P0 : 0.f;
                *(float4*)(pbase + (size_t)r*2048 + s2*128 + (c4 << 2)) =
                    make_float4(pv, pv, pv, pv);
            }
        }
    }
    // epilogue AV on last block
    __syncthreads();
    {
        int il = nproc - 1;
        uint pb2 = sb + ((il & 1) ? OFF_P1 : OFF_P0);
        int vm3 = il % 3;
        uint vb2 = sb + (vm3 == 0 ? voffs0 : (vm3 == 1 ? voffs1 : voffs2));
        #pragma unroll
        for (int ks = 0; ks < 8; ks++) {
            uint4 Ah = ldsm4(pb2 + VOFF(aRow, 2*ks + aChS));
            #pragma unroll
            for (int fp = 0; fp < 2; fp++) {
                int cch = ((db + 16*fp) >> 3) + vChS;
                uint4 Bh = ldsm4t(vb2 + QOFF(16*ks + vRowOff, cch));
                mma16816(accAV[2*fp],     Ah, Bh.x, Bh.y);
                mma16816(accAV[2*fp + 1], Ah, Bh.z, Bh.w);
            }
        }
    }

    if (!anyU) {
        for (int s2 = 0; s2 < 16; s2++) {
            if ((vmask >> s2) & 1) continue;
            float4 z = make_float4(0.f, 0.f, 0.f, 0.f);
            for (int i2 = tid; i2 < 4096; i2 += 512) {
                int r = i2 >> 5, c4 = i2 & 31;
                *(float4*)(pbase + (size_t)r*2048 + s2*128 + (c4 << 2)) = z;
            }
        }
    }

    {
        float* cb = ctx + ((size_t)(b*2048 + s*128))*64;
        #pragma unroll
        for (int f = 0; f < 2; f++) {
            int dc = db + 8*f + 2*lq;
            *(float2*)(cb + (size_t)rA*64 + dc) = make_float2(accAV[f][0], accAV[f][1]);
            *(float2*)(cb + (size_t)rB*64 + dc) = make_float2(accAV[f][2], accAV[f][3]);
        }
        #pragma unroll
        for (int f = 2; f < 4; f++) {
            int dc = db + 8*(f-2) + 16 + 2*lq;
            *(float2*)(cb + (size_t)rA*64 + dc) = make_float2(accAV[f][0], accAV[f][1]);
            *(float2*)(cb + (size_t)rB*64 + dc) = make_float2(accAV[f][2], accAV[f][3]);
        }
    }
}

extern "C" void kernel_launch(void* const* d_in, const int* in_sizes, int n_in,
                              void* d_out, int out_size) {
    const float* x    = (const float*)d_in[0];
    const int*   tags = (const int*)  d_in[1];
    const float* mk   = (const float*)d_in[2];
    const float* Wk_w = (const float*)d_in[3];
    const float* Wk_b = (const float*)d_in[4];
    const float* Wq_w = (const float*)d_in[5];
    const float* Wq_b = (const float*)d_in[6];
    const float* Wv_w = (const float*)d_in[7];
    const float* Wv_b = (const float*)d_in[8];

    float* ctx = (float*)d_out;                        // [8,16,128,64]
    float* p   = ctx + (size_t)BB*SS*TT*DD;            // [8,2048,2048]

    cudaFuncSetAttribute(qkv_kernel,  cudaFuncAttributeMaxDynamicSharedMemorySize, SMEM_QKV);
    cudaFuncSetAttribute(attn_kernel, cudaFuncAttributeMaxDynamicSharedMemorySize, SMEM_AT);

    qkv_kernel<<<128, 512, SMEM_QKV>>>(x, Wq_w, Wq_b, Wk_w, Wk_b, Wv_w, Wv_b);
    attn_kernel<<<dim3(SS, BB), 512, SMEM_AT>>>(tags, mk, ctx, p);
}

// round 16
// speedup vs baseline: 1.7431x; 1.1377x over previous
#include <cuda_runtime.h>
#include <cuda_fp16.h>

#define BB 8
#define SS 16
#define TT 128
#define DD 64
#define NN 2048
#define P0  (0.00048828125f)   // 1/2048
#define C2E (0.18033688011112042f)   // 0.125 * log2(e)

typedef unsigned long long ull;
typedef unsigned int uint;

// fp16 split operands
__device__ __half g_qh[BB*NN*DD], g_ql[BB*NN*DD];
__device__ __half g_kh[BB*NN*DD], g_kl[BB*NN*DD];
__device__ __half g_vph[BB*NN*DD];            // [b][m][d] single fp16, m = t*16+s

#define QOFF(r,c) ((uint)((r)*128 + (((c) ^ ((r)&7)) << 4)))
#define VOFF(r,c) ((uint)((r)*256 + (((c) ^ ((r)&7)) << 4)))

__device__ __forceinline__ uint smem_u32(const void* p){
    uint a; asm("{ .reg .u64 t; cvta.to.shared.u64 t, %1; cvt.u32.u64 %0, t; }" : "=r"(a) : "l"(p));
    return a;
}
__device__ __forceinline__ void cpa16(uint dst, const void* src){
    asm volatile("cp.async.cg.shared.global [%0], [%1], 16;"
        :: "r"(dst), "l"(__cvta_generic_to_global(src)) : "memory");
}
#define CPA_COMMIT() asm volatile("cp.async.commit_group;" ::: "memory")
#define CPA_WAIT0()  asm volatile("cp.async.wait_group 0;" ::: "memory")

__device__ __forceinline__ uint4 ldsm4(uint addr){
    uint4 r;
    asm volatile("ldmatrix.sync.aligned.m8n8.x4.shared.b16 {%0,%1,%2,%3}, [%4];"
        : "=r"(r.x), "=r"(r.y), "=r"(r.z), "=r"(r.w) : "r"(addr));
    return r;
}
__device__ __forceinline__ uint4 ldsm4t(uint addr){
    uint4 r;
    asm volatile("ldmatrix.sync.aligned.m8n8.x4.trans.shared.b16 {%0,%1,%2,%3}, [%4];"
        : "=r"(r.x), "=r"(r.y), "=r"(r.z), "=r"(r.w) : "r"(addr));
    return r;
}
__device__ __forceinline__ void mma16816(float* d, uint4 a, uint b0, uint b1){
    asm volatile("mma.sync.aligned.m16n8k16.row.col.f32.f16.f16.f32 "
        "{%0,%1,%2,%3}, {%4,%5,%6,%7}, {%8,%9}, {%0,%1,%2,%3};"
        : "+f"(d[0]), "+f"(d[1]), "+f"(d[2]), "+f"(d[3])
        : "r"(a.x), "r"(a.y), "r"(a.z), "r"(a.w), "r"(b0), "r"(b1));
}
__device__ __forceinline__ float ex2f(float x){
    float r; asm("ex2.approx.f32 %0, %1;" : "=f"(r) : "f"(x)); return r;
}
__device__ __forceinline__ uint ex2h2(uint x){
    uint r; asm("ex2.approx.f16x2 %0, %1;" : "=r"(r) : "r"(x)); return r;
}

// ---------------- kernel 1: QKV projection via mma.sync ----------------
#define QK_XH 0
#define QK_XL 16384
#define QK_WH 32768
#define QK_WL 57344
#define QK_BS 81920
#define SMEM_QKV 82944

__global__ void __launch_bounds__(512)
qkv_kernel(const float* __restrict__ x,
           const float* __restrict__ Wq_w, const float* __restrict__ Wq_b,
           const float* __restrict__ Wk_w, const float* __restrict__ Wk_b,
           const float* __restrict__ Wv_w, const float* __restrict__ Wv_b)
{
    extern __shared__ char smq[];
    uint sb = smem_u32(smq);
    float* bs = (float*)(smq + QK_BS);
    int tid = threadIdx.x;
    int gr0 = blockIdx.x * 128;
    int b_  = blockIdx.x >> 4;
    int s_  = blockIdx.x & 15;

    #pragma unroll
    for (int it = 0; it < 2; it++) {
        int idx = tid + (it << 9);
        int r = idx >> 3, c = idx & 7;
        const float* src = x + (size_t)(gr0 + r)*64 + c*8;
        float4 v0 = *(const float4*)src;
        float4 v1 = *(const float4*)(src + 4);
        float f[8] = {v0.x,v0.y,v0.z,v0.w,v1.x,v1.y,v1.z,v1.w};
        __half h[8], lo[8];
        #pragma unroll
        for (int i = 0; i < 8; i++) {
            h[i]  = __float2half_rn(f[i]);
            lo[i] = __float2half_rn(f[i] - __half2float(h[i]));
        }
        *(uint4*)(smq + QK_XH + QOFF(r, c)) = *(uint4*)h;
        *(uint4*)(smq + QK_XL + QOFF(r, c)) = *(uint4*)lo;
    }
    #pragma unroll
    for (int it = 0; it < 3; it++) {
        int idx = tid + it*512;
        int n = idx >> 3, c = idx & 7;
        const float* wsrc = (n < 64) ? Wq_w : ((n < 128) ? Wk_w : Wv_w);
        const float* src = wsrc + (size_t)(n & 63)*64 + c*8;
        float4 v0 = *(const float4*)src;
        float4 v1 = *(const float4*)(src + 4);
        float f[8] = {v0.x,v0.y,v0.z,v0.w,v1.x,v1.y,v1.z,v1.w};
        __half h[8], lo[8];
        #pragma unroll
        for (int i = 0; i < 8; i++) {
            h[i]  = __float2half_rn(f[i]);
            lo[i] = __float2half_rn(f[i] - __half2float(h[i]));
        }
        *(uint4*)(smq + QK_WH + QOFF(n, c)) = *(uint4*)h;
        *(uint4*)(smq + QK_WL + QOFF(n, c)) = *(uint4*)lo;
    }
    if (tid < 192)
        bs[tid] = (tid < 64) ? Wq_b[tid] : ((tid < 128) ? Wk_b[tid-64] : Wv_b[tid-128]);
    __syncthreads();

    int wid  = tid >> 5, lane = tid & 31;
    int wr   = wid >> 1;
    int wh   = wid & 1;
    int m0   = wr << 4;
    int nb   = wh * 96;
    int lq   = lane & 3;
    int lr   = lane >> 2;
    int rA   = m0 + lr, rB = rA + 8;
    int aRow = m0 + (lane & 7) + ((lane >> 3) & 1)*8;
    int aChS = (lane >> 4);
    int bRowOff = (lane & 7) + ((lane >= 16) ? 8 : 0);
    int bChS = ((lane >> 3) & 1);

    float acc[12][4];
    #pragma unroll
    for (int f = 0; f < 12; f++) { acc[f][0]=0; acc[f][1]=0; acc[f][2]=0; acc[f][3]=0; }

    #pragma unroll
    for (int ks = 0; ks < 4; ks++) {
        uint4 Ah = ldsm4(sb + QK_XH + QOFF(aRow, 2*ks + aChS));
        uint4 Al = ldsm4(sb + QK_XL + QOFF(aRow, 2*ks + aChS));
        #pragma unroll
        for (int fp = 0; fp < 6; fp++) {
            int n = nb + 16*fp;
            uint4 Bh = ldsm4(sb + QK_WH + QOFF(n + bRowOff, 2*ks + bChS));
            mma16816(acc[2*fp],     Ah, Bh.x, Bh.y);
            mma16816(acc[2*fp + 1], Ah, Bh.z, Bh.w);
            mma16816(acc[2*fp],     Al, Bh.x, Bh.y);
            mma16816(acc[2*fp + 1], Al, Bh.z, Bh.w);
            uint4 Bl = ldsm4(sb + QK_WL + QOFF(n + bRowOff, 2*ks + bChS));
            mma16816(acc[2*fp],     Ah, Bl.x, Bl.y);
            mma16816(acc[2*fp + 1], Ah, Bl.z, Bl.w);
        }
    }

    #pragma unroll
    for (int f = 0; f < 12; f++) {
        int col0 = nb + 8*f + 2*lq;
        int mat  = col0 >> 6;
        int cc   = col0 & 63;
        float b0 = bs[col0], b1 = bs[col0 + 1];
        float vA0 = acc[f][0] + b0, vA1 = acc[f][1] + b1;
        float vB0 = acc[f][2] + b0, vB1 = acc[f][3] + b1;
        __half hA0 = __float2half_rn(vA0), hA1 = __float2half_rn(vA1);
        __half hB0 = __float2half_rn(vB0), hB1 = __float2half_rn(vB1);
        if (mat < 2) {
            __half* dh = mat ? g_kh : g_qh;
            __half* dl = mat ? g_kl : g_ql;
            __half2 hA(hA0, hA1), hB(hB0, hB1);
            __half2 lA(__float2half_rn(vA0 - __half2float(hA0)),
                       __float2half_rn(vA1 - __half2float(hA1)));
            __half2 lB(__float2half_rn(vB0 - __half2float(hB0)),
                       __float2half_rn(vB1 - __half2float(hB1)));
            *(uint*)(dh + (size_t)(gr0 + rA)*64 + cc) = *(uint*)&hA;
            *(uint*)(dh + (size_t)(gr0 + rB)*64 + cc) = *(uint*)&hB;
            *(uint*)(dl + (size_t)(gr0 + rA)*64 + cc) = *(uint*)&lA;
            *(uint*)(dl + (size_t)(gr0 + rB)*64 + cc) = *(uint*)&lB;
        } else {
            int mA = rA*16 + s_, mB = rB*16 + s_;
            __half2 hA(hA0, hA1), hB(hB0, hB1);
            *(uint*)(g_vph + ((size_t)(b_ << 11) + mA)*64 + cc) = *(uint*)&hA;
            *(uint*)(g_vph + ((size_t)(b_ << 11) + mB)*64 + cc) = *(uint*)&hB;
        }
    }
}

// ---------------- attention (512 threads, fp16, single-sync pipeline) ----------------
#define OFF_QH 0
#define OFF_QL 16384
#define OFF_K0 32768
#define OFF_K0L 49152
#define OFF_K1 65536
#define OFF_K1L 81920
#define OFF_V0 98304
#define OFF_V1 114688
#define OFF_V2 131072
#define OFF_P0 147456
#define OFF_P1 180224
#define OFF_MSB  212992
#define OFF_STLP 215040
#define OFF_UF   216064
#define OFF_FLAG 216576
#define OFF_TAGS 216580
#define SMEM_AT  216704

__global__ void __launch_bounds__(512, 1)
attn_kernel(const int* __restrict__ tags, const float* __restrict__ mask,
            float* __restrict__ ctx, float* __restrict__ p)
{
    extern __shared__ char smem[];
    uint sb = smem_u32(smem);
    int tid  = threadIdx.x;
    int wid  = tid >> 5, lane = tid & 31;
    int wr   = wid >> 1;
    int wh   = wid & 1;
    int m0   = wr << 4;
    int nb   = wh << 6;
    int db   = wh << 5;
    int s    = blockIdx.x;
    int b    = blockIdx.y;
    int lq   = lane & 3;
    int lr   = lane >> 2;
    int rA   = m0 + lr, rB = rA + 8;

    int*   tgs  = (int*)(smem + OFF_TAGS);
    uint*  msb  = (uint*)(smem + OFF_MSB);
    float* stlp = (float*)(smem + OFF_STLP);
    int*   ufr  = (int*)(smem + OFF_UF);
    int*   flg  = (int*)(smem + OFF_FLAG);

    if (tid < 16) tgs[tid] = tags[b*16 + tid];
    if (tid == 0) flg[0] = 0;
    {
        int tt = tid >> 2, w = tid & 3;
        uint bits = 0;
        #pragma unroll 8
        for (int j = 0; j < 32; j++)
            bits |= (mask[(size_t)tt*128 + w*32 + j] != 0.f ? 1u : 0u) << j;
        msb[tid] = bits;
    }
    // stage Q hi+lo
    #pragma unroll
    for (int it = 0; it < 2; it++) {
        int idx = tid + (it << 9);
        int r = idx >> 3, c = idx & 7;
        size_t se = ((size_t)((b << 11) + (s << 7) + r))*64 + c*8;
        cpa16(sb + OFF_QH + QOFF(r, c), g_qh + se);
        cpa16(sb + OFF_QL + QOFF(r, c), g_ql + se);
    }
    CPA_COMMIT();
    __syncthreads();

    int mytag = tgs[s];
    uint vmask = 0;
    #pragma unroll
    for (int s2 = 0; s2 < 16; s2++) if (tgs[s2] == mytag) vmask |= 1u << s2;
    int vlist[16], nv = 0;
    #pragma unroll
    for (int s2 = 0; s2 < 16; s2++) if ((vmask >> s2) & 1) vlist[nv++] = s2;

    uint mbA = 0, mbB = 0;
    #pragma unroll
    for (int f = 0; f < 8; f++)
        #pragma unroll
        for (int u = 0; u < 2; u++) {
            int cw = nb + 8*f + 2*lq + u;
            mbA |= ((msb[rA*4 + (cw >> 5)] >> (cw & 31)) & 1u) << (f*2 + u);
            mbB |= ((msb[rB*4 + (cw >> 5)] >> (cw & 31)) & 1u) << (f*2 + u);
        }
    int fullm = (mbA == 0xffffu) && (mbB == 0xffffu);

    int aRow = m0 + (lane & 7) + ((lane >> 3) & 1)*8;
    int aChS = (lane >> 4);
    int bRowOff = (lane & 7) + ((lane >= 16) ? 8 : 0);
    int bChS = ((lane >> 3) & 1);
    int vRowOff = (lane & 7) + (((lane >> 3) & 1) << 3);
    int vChS = (lane >> 4);

    const __half* gb_kh = g_kh + ((size_t)b << 17);
    const __half* gb_kl = g_kl + ((size_t)b << 17);
    const __half* gb_vh = g_vph + ((size_t)b << 17);

    // ================ pass 1: l = sum exp(s), hi-only QK ================
    float lsA = 0.f, lsB = 0.f;
    {
        #pragma unroll
        for (int it = 0; it < 2; it++) {
            int idx = tid + (it << 9);
            int r = idx >> 3, c = idx & 7;
            cpa16(sb + OFF_K0 + QOFF(r, c), gb_kh + ((size_t)((vlist[0] << 7) + r))*64 + c*8);
        }
        CPA_COMMIT();
        for (int vi = 0; vi < nv; vi++) {
            CPA_WAIT0();
            __syncthreads();
            if (vi + 1 < nv) {
                uint dsto = ((vi + 1) & 1) ? OFF_K1 : OFF_K0;
                #pragma unroll
                for (int it = 0; it < 2; it++) {
                    int idx = tid + (it << 9);
                    int r = idx >> 3, c = idx & 7;
                    cpa16(sb + dsto + QOFF(r, c), gb_kh + ((size_t)((vlist[vi+1] << 7) + r))*64 + c*8);
                }
                CPA_COMMIT();
            }
            uint kb = sb + ((vi & 1) ? OFF_K1 : OFF_K0);
            float acc[8][4];
            #pragma unroll
            for (int f = 0; f < 8; f++) { acc[f][0]=0; acc[f][1]=0; acc[f][2]=0; acc[f][3]=0; }
            #pragma unroll
            for (int ks = 0; ks < 4; ks++) {
                uint4 Ah = ldsm4(sb + OFF_QH + QOFF(aRow, 2*ks + aChS));
                #pragma unroll
                for (int fp = 0; fp < 4; fp++) {
                    int n = nb + 16*fp;
                    uint4 Bv = ldsm4(kb + QOFF(n + bRowOff, 2*ks + bChS));
                    mma16816(acc[2*fp],     Ah, Bv.x, Bv.y);
                    mma16816(acc[2*fp + 1], Ah, Bv.z, Bv.w);
                }
            }
            if (fullm) {
                // packed f16x2 ex2, fold to fp32 once per block
                __half2 hsA = __floats2half2_rn(0.f, 0.f);
                __half2 hsB = hsA;
                #pragma unroll
                for (int f = 0; f < 8; f++) {
                    __half2 aA = __floats2half2_rn(acc[f][0]*C2E, acc[f][1]*C2E);
                    __half2 aB = __floats2half2_rn(acc[f][2]*C2E, acc[f][3]*C2E);
                    uint eA = ex2h2(*(uint*)&aA);
                    uint eB = ex2h2(*(uint*)&aB);
                    hsA = __hadd2(hsA, *(__half2*)&eA);
                    hsB = __hadd2(hsB, *(__half2*)&eB);
                }
                float2 fA = __half22float2(hsA), fB = __half22float2(hsB);
                lsA += fA.x + fA.y;
                lsB += fB.x + fB.y;
            } else {
                #pragma unroll
                for (int f = 0; f < 8; f++) {
                    lsA += (((mbA >> (2*f)) & 1)   ? ex2f(acc[f][0]*C2E) : 0.f)
                         + (((mbA >> (2*f+1)) & 1) ? ex2f(acc[f][1]*C2E) : 0.f);
                    lsB += (((mbB >> (2*f)) & 1)   ? ex2f(acc[f][2]*C2E) : 0.f)
                         + (((mbB >> (2*f+1)) & 1) ? ex2f(acc[f][3]*C2E) : 0.f);
                }
            }
        }
    }
    // prefetch pass-2 block 0 (K hi+lo, V) while reducing
    #pragma unroll
    for (int it = 0; it < 2; it++) {
        int idx = tid + (it << 9);
        int r = idx >> 3, c = idx & 7;
        size_t se = ((size_t)((vlist[0] << 7) + r))*64 + c*8;
        cpa16(sb + OFF_K0  + QOFF(r, c), gb_kh + se);
        cpa16(sb + OFF_K0L + QOFF(r, c), gb_kl + se);
        cpa16(sb + OFF_V0  + QOFF(r, c), gb_vh + se);
    }
    CPA_COMMIT();

    lsA += __shfl_xor_sync(0xffffffffu, lsA, 1);
    lsA += __shfl_xor_sync(0xffffffffu, lsA, 2);
    lsB += __shfl_xor_sync(0xffffffffu, lsB, 1);
    lsB += __shfl_xor_sync(0xffffffffu, lsB, 2);
    __syncthreads();
    if (lq == 0) { stlp[rA*2 + wh] = lsA; stlp[rB*2 + wh] = lsB; }
    __syncthreads();
    float lA = stlp[rA*2] + stlp[rA*2+1];
    float lB = stlp[rB*2] + stlp[rB*2+1];
    int ufA = (lA == 0.f), ufB = (lB == 0.f);
    float invlA = ufA ? 0.f : 1.f/lA;
    float invlB = ufB ? 0.f : 1.f/lB;
    if (lq == 0 && wh == 0) { ufr[rA] = ufA; ufr[rB] = ufB; if (ufA | ufB) flg[0] = 1; }
    __syncthreads();
    int anyU = flg[0];
    if (anyU) {
        #pragma unroll
        for (int it = 0; it < 2; it++) {
            int idx = tid + (it << 9);
            int r = idx >> 3, c = idx & 7;
            size_t se = ((size_t)r)*64 + c*8;
            cpa16(sb + OFF_K0  + QOFF(r, c), gb_kh + se);
            cpa16(sb + OFF_K0L + QOFF(r, c), gb_kl + se);
            cpa16(sb + OFF_V0  + QOFF(r, c), gb_vh + se);
        }
        CPA_COMMIT();
    }

    // ================ pass 2: single sync per block, deferred AV ================
    int nproc = anyU ? 16 : nv;
    float accAV[4][4];
    #pragma unroll
    for (int f = 0; f < 4; f++) { accAV[f][0]=0; accAV[f][1]=0; accAV[f][2]=0; accAV[f][3]=0; }
    float* pbase = p + ((size_t)(b*2048 + s*128))*2048;
    const uint voffs0 = OFF_V0, voffs1 = OFF_V1, voffs2 = OFF_V2;

    for (int i = 0; i < nproc; i++) {
        int s2 = anyU ? i : vlist[i];
        int bv = (vmask >> s2) & 1;
        CPA_WAIT0();
        __syncthreads();   // K(i),V(i) ready; P(i-1) visible
        // deferred AV on block i-1
        if (i > 0) {
            uint pb2 = sb + (((i-1) & 1) ? OFF_P1 : OFF_P0);
            int vm3 = (i-1) % 3;
            uint vb2 = sb + (vm3 == 0 ? voffs0 : (vm3 == 1 ? voffs1 : voffs2));
            #pragma unroll
            for (int ks = 0; ks < 8; ks++) {
                uint4 Ah = ldsm4(pb2 + VOFF(aRow, 2*ks + aChS));
                #pragma unroll
                for (int fp = 0; fp < 2; fp++) {
                    int cch = ((db + 16*fp) >> 3) + vChS;
                    uint4 Bh = ldsm4t(vb2 + QOFF(16*ks + vRowOff, cch));
                    mma16816(accAV[2*fp],     Ah, Bh.x, Bh.y);
                    mma16816(accAV[2*fp + 1], Ah, Bh.z, Bh.w);
                }
            }
        }
        // prefetch block i+1
        if (i + 1 < nproc) {
            int s3 = anyU ? (i + 1) : vlist[i + 1];
            uint dh = ((i + 1) & 1) ? OFF_K1 : OFF_K0;
            uint dl = ((i + 1) & 1) ? OFF_K1L : OFF_K0L;
            int vn3 = (i + 1) % 3;
            uint dv = (vn3 == 0 ? voffs0 : (vn3 == 1 ? voffs1 : voffs2));
            #pragma unroll
            for (int it = 0; it < 2; it++) {
                int idx = tid + (it << 9);
                int r = idx >> 3, c = idx & 7;
                size_t se = ((size_t)((s3 << 7) + r))*64 + c*8;
                cpa16(sb + dh + QOFF(r, c), gb_kh + se);
                cpa16(sb + dl + QOFF(r, c), gb_kl + se);
                cpa16(sb + dv + QOFF(r, c), gb_vh + se);
            }
            CPA_COMMIT();
        }
        uint kbh = sb + ((i & 1) ? OFF_K1 : OFF_K0);
        uint kbl = sb + ((i & 1) ? OFF_K1L : OFF_K0L);
        uint pcur = sb + ((i & 1) ? OFF_P1 : OFF_P0);
        if (bv) {
            float acc[8][4];
            #pragma unroll
            for (int f = 0; f < 8; f++) { acc[f][0]=0; acc[f][1]=0; acc[f][2]=0; acc[f][3]=0; }
            #pragma unroll
            for (int ks = 0; ks < 4; ks++) {
                uint4 Ah = ldsm4(sb + OFF_QH + QOFF(aRow, 2*ks + aChS));
                uint4 Al = ldsm4(sb + OFF_QL + QOFF(aRow, 2*ks + aChS));
                #pragma unroll
                for (int fp = 0; fp < 4; fp++) {
                    int n = nb + 16*fp;
                    uint4 Bh = ldsm4(kbh + QOFF(n + bRowOff, 2*ks + bChS));
                    mma16816(acc[2*fp],     Ah, Bh.x, Bh.y);
                    mma16816(acc[2*fp + 1], Ah, Bh.z, Bh.w);
                    mma16816(acc[2*fp],     Al, Bh.x, Bh.y);
                    mma16816(acc[2*fp + 1], Al, Bh.z, Bh.w);
                    uint4 Bl = ldsm4(kbl + QOFF(n + bRowOff, 2*ks + bChS));
                    mma16816(acc[2*fp],     Ah, Bl.x, Bl.y);
                    mma16816(acc[2*fp + 1], Ah, Bl.z, Bl.w);
                }
            }
            #pragma unroll
            for (int f = 0; f < 8; f++) {
                float e0, e1, e2, e3;
                if (fullm) {
                    e0 = ex2f(acc[f][0]*C2E);
                    e1 = ex2f(acc[f][1]*C2E);
                    e2 = ex2f(acc[f][2]*C2E);
                    e3 = ex2f(acc[f][3]*C2E);
                } else {
                    e0 = ((mbA >> (2*f)) & 1)   ? ex2f(acc[f][0]*C2E) : 0.f;
                    e1 = ((mbA >> (2*f+1)) & 1) ? ex2f(acc[f][1]*C2E) : 0.f;
                    e2 = ((mbB >> (2*f)) & 1)   ? ex2f(acc[f][2]*C2E) : 0.f;
                    e3 = ((mbB >> (2*f+1)) & 1) ? ex2f(acc[f][3]*C2E) : 0.f;
                }
                float p0 = ufA ? P0 : e0*invlA;
                float p1 = ufA ? P0 : e1*invlA;
                float p2 = ufB ? P0 : e2*invlB;
                float p3 = ufB ? P0 : e3*invlB;
                int cw = nb + 8*f + 2*lq;
                __stcs((float2*)(pbase + (size_t)rA*2048 + s2*128 + cw), make_float2(p0, p1));
                __stcs((float2*)(pbase + (size_t)rB*2048 + s2*128 + cw), make_float2(p2, p3));
                int ch = (wh << 3) + f;
                __half2 hA = __floats2half2_rn(p0, p1);
                __half2 hB = __floats2half2_rn(p2, p3);
                *(uint*)(smem + (pcur - sb) + VOFF(rA, ch) + 4*lq) = *(uint*)&hA;
                *(uint*)(smem + (pcur - sb) + VOFF(rB, ch) + 4*lq) = *(uint*)&hB;
            }
        } else {
            for (int i2 = tid; i2 < 2048; i2 += 512) {
                int r = i2 >> 4, c = i2 & 15;
                float pv = ufr[r] ? P0 : 0.f;
                __half2 hv2 = __floats2half2_rn(pv, pv);
                uint hw = *(uint*)&hv2;
                uint4 hv; hv.x = hv.y = hv.z = hv.w = hw;
                *(uint4*)(smem + (pcur - sb) + VOFF(r, c)) = hv;
            }
            for (int i2 = tid; i2 < 4096; i2 += 512) {
                int r = i2 >> 5, c4 = i2 & 31;
                float pv = ufr[r] ? P0 : 0.f;
                __stcs((float4*)(pbase + (size_t)r*2048 + s2*128 + (c4 << 2)),
                       make_float4(pv, pv, pv, pv));
            }
        }
    }
    // epilogue AV on last block
    __syncthreads();
    {
        int il = nproc - 1;
        uint pb2 = sb + ((il & 1) ? OFF_P1 : OFF_P0);
        int vm3 = il % 3;
        uint vb2 = sb + (vm3 == 0 ? voffs0 : (vm3 == 1 ? voffs1 : voffs2));
        #pragma unroll
        for (int ks = 0; ks < 8; ks++) {
            uint4 Ah = ldsm4(pb2 + VOFF(aRow, 2*ks + aChS));
            #pragma unroll
            for (int fp = 0; fp < 2; fp++) {
                int cch = ((db + 16*fp) >> 3) + vChS;
                uint4 Bh = ldsm4t(vb2 + QOFF(16*ks + vRowOff, cch));
                mma16816(accAV[2*fp],     Ah, Bh.x, Bh.y);
                mma16816(accAV[2*fp + 1], Ah, Bh.z, Bh.w);
            }
        }
    }

    if (!anyU) {
        for (int s2 = 0; s2 < 16; s2++) {
            if ((vmask >> s2) & 1) continue;
            float4 z = make_float4(0.f, 0.f, 0.f, 0.f);
            for (int i2 = tid; i2 < 4096; i2 += 512) {
                int r = i2 >> 5, c4 = i2 & 31;
                __stcs((float4*)(pbase + (size_t)r*2048 + s2*128 + (c4 << 2)), z);
            }
        }
    }

    {
        float* cb = ctx + ((size_t)(b*2048 + s*128))*64;
        #pragma unroll
        for (int f = 0; f < 2; f++) {
            int dc = db + 8*f + 2*lq;
            __stcs((float2*)(cb + (size_t)rA*64 + dc), make_float2(accAV[f][0], accAV[f][1]));
            __stcs((float2*)(cb + (size_t)rB*64 + dc), make_float2(accAV[f][2], accAV[f][3]));
        }
        #pragma unroll
        for (int f = 2; f < 4; f++) {
            int dc = db + 8*(f-2) + 16 + 2*lq;
            __stcs((float2*)(cb + (size_t)rA*64 + dc), make_float2(accAV[f][0], accAV[f][1]));
            __stcs((float2*)(cb + (size_t)rB*64 + dc), make_float2(accAV[f][2], accAV[f][3]));
        }
    }
}

extern "C" void kernel_launch(void* const* d_in, const int* in_sizes, int n_in,
                              void* d_out, int out_size) {
    const float* x    = (const float*)d_in[0];
    const int*   tags = (const int*)  d_in[1];
    const float* mk   = (const float*)d_in[2];
    const float* Wk_w = (const float*)d_in[3];
    const float* Wk_b = (const float*)d_in[4];
    const float* Wq_w = (const float*)d_in[5];
    const float* Wq_b = (const float*)d_in[6];
    const float* Wv_w = (const float*)d_in[7];
    const float* Wv_b = (const float*)d_in[8];

    float* ctx = (float*)d_out;                        // [8,16,128,64]
    float* p   = ctx + (size_t)BB*SS*TT*DD;            // [8,2048,2048]

    cudaFuncSetAttribute(qkv_kernel,  cudaFuncAttributeMaxDynamicSharedMemorySize, SMEM_QKV);
    cudaFuncSetAttribute(attn_kernel, cudaFuncAttributeMaxDynamicSharedMemorySize, SMEM_AT);

    qkv_kernel<<<128, 512, SMEM_QKV>>>(x, Wq_w, Wq_b, Wk_w, Wk_b, Wv_w, Wv_b);
    attn_kernel<<<dim3(SS, BB), 512, SMEM_AT>>>(tags, mk, ctx, p);
}